// round 3
// baseline (speedup 1.0000x reference)
#include <cuda_runtime.h>
#include <math.h>

// Fixed problem shape
#define HH 128
#define GG 64
#define LL 2
#define NN_MAX 100000

// Scratch: __device__ globals (allocation-free per harness rules).
// NOTE: these are ONLY referenced inside device code (never passed as kernel
// arguments from host — host-side __device__ symbol use is invalid).
__device__ float g_h[NN_MAX * HH];
__device__ float g_aggr[NN_MAX * HH];
__device__ float g_tmp[NN_MAX * HH];
__device__ float g_pool[GG * HH];
__device__ float g_cnt[GG];
__device__ float g_st[GG * 64];
__device__ int   g_idx64;   // 1 if edge_index/batch are int64, 0 if int32

// Buffer selectors for the GEMM template
#define BUF_AGGR 0
#define BUF_TMP  1
#define BUF_H    2

__device__ __forceinline__ float* buf_ptr(int sel) {
    return sel == BUF_AGGR ? g_aggr : (sel == BUF_TMP ? g_tmp : g_h);
}

// ---------------------------------------------------------------------------
// dtype detect: reinterpret first 16 int64 slots of edge_index. If the data is
// really int32, each int64 combines two random indices -> hi word nonzero with
// prob ~(1-1e-5) per slot -> some value >= n. If genuinely int64, all < n.
__global__ void detect_kernel(const void* ei_raw, int n) {
    if (threadIdx.x == 0 && blockIdx.x == 0) {
        const long long* p = (const long long*)ei_raw;
        int ok = 1;
        for (int i = 0; i < 16; i++) {
            long long v = p[i];
            if (v < 0 || v >= (long long)n) ok = 0;
        }
        g_idx64 = ok;
    }
}

// ---------------------------------------------------------------------------
// h = x @ enc_w + enc_b (rank-1)
__global__ void encode_kernel(const float* __restrict__ x,
                              const float* __restrict__ enc_w,
                              const float* __restrict__ enc_b, int n) {
    int idx = blockIdx.x * blockDim.x + threadIdx.x;   // n*32 threads
    if (idx >= n * 32) return;
    int i = idx >> 5;
    int c = (idx & 31) * 4;
    float xv = __ldg(x + i);
    float4 w = *(const float4*)(enc_w + c);
    float4 b = *(const float4*)(enc_b + c);
    float4 r;
    r.x = fmaf(xv, w.x, b.x);
    r.y = fmaf(xv, w.y, b.y);
    r.z = fmaf(xv, w.z, b.z);
    r.w = fmaf(xv, w.w, b.w);
    *(float4*)(g_h + (size_t)i * HH + c) = r;
}

// ---------------------------------------------------------------------------
// aggr = (1 + eps[l]) * h
__global__ void init_aggr_kernel(const float* __restrict__ eps_l, int n) {
    int idx = blockIdx.x * blockDim.x + threadIdx.x;   // n*32 float4 slots
    if (idx >= n * 32) return;
    float s = 1.0f + __ldg(eps_l);
    float4 v = ((const float4*)g_h)[idx];
    v.x *= s; v.y *= s; v.z *= s; v.w *= s;
    ((float4*)g_aggr)[idx] = v;
}

// ---------------------------------------------------------------------------
// One warp per edge: msg = relu(h[src] + edge_attr*edge_w + edge_b),
// scalar atomicAdd into aggr[dst] (4 per lane).
__global__ void scatter_kernel(const void* __restrict__ ei_raw,
                               const float* __restrict__ edge_attr,
                               const float* __restrict__ edge_w,
                               const float* __restrict__ edge_b,
                               int E, int n) {
    int gt = blockIdx.x * blockDim.x + threadIdx.x;
    int e = gt >> 5;
    if (e >= E) return;
    int lane = gt & 31;
    long long src, dst;
    if (g_idx64) {
        const long long* ei = (const long long*)ei_raw;
        src = __ldg(ei + e);
        dst = __ldg(ei + E + e);
    } else {
        const int* ei = (const int*)ei_raw;
        src = __ldg(ei + e);
        dst = __ldg(ei + E + e);
    }
    if ((unsigned long long)src >= (unsigned long long)n ||
        (unsigned long long)dst >= (unsigned long long)n) return;  // safety
    float ea = __ldg(edge_attr + e);
    int c = lane * 4;
    float4 hv = *(const float4*)(g_h + (size_t)src * HH + c);
    float4 ew = *(const float4*)(edge_w + c);
    float4 eb = *(const float4*)(edge_b + c);
    float* dp = g_aggr + (size_t)dst * HH + c;
    atomicAdd(dp + 0, fmaxf(hv.x + fmaf(ea, ew.x, eb.x), 0.0f));
    atomicAdd(dp + 1, fmaxf(hv.y + fmaf(ea, ew.y, eb.y), 0.0f));
    atomicAdd(dp + 2, fmaxf(hv.z + fmaf(ea, ew.z, eb.z), 0.0f));
    atomicAdd(dp + 3, fmaxf(hv.w + fmaf(ea, ew.w, eb.w), 0.0f));
}

// ---------------------------------------------------------------------------
// C[M,128] = act(A[M,128] @ W[128,128] + bias), optional BN epilogue.
// A and C are selected from the __device__ scratch buffers INSIDE device code
// (SRC/DST template ints) — never passed from host.
// 256 threads, 128x128 block tile, 8x8 per-thread, BK=32, static smem only.
template <int MODE, int SRC, int DST>
__global__ void gemm128_kernel(const float* __restrict__ W,
                               const float* __restrict__ bias,
                               const float* __restrict__ bn_g,
                               const float* __restrict__ bn_b,
                               const float* __restrict__ bn_m,
                               const float* __restrict__ bn_v,
                               int M) {
    const float* A = buf_ptr(SRC);
    float*       C = buf_ptr(DST);

    __shared__ float sW[32 * HH];    // sW[kk*128 + c]
    __shared__ float sA[32 * 129];   // sA[kk*129 + r] (pad to kill conflicts)
    int tid = threadIdx.x;           // 256
    int tx = tid & 15;               // cols: tx + 16*j
    int ty = tid >> 4;               // rows: ty*8 + i
    int row0 = blockIdx.x * 128;

    float acc[8][8];
    #pragma unroll
    for (int i = 0; i < 8; i++)
        #pragma unroll
        for (int j = 0; j < 8; j++) acc[i][j] = 0.0f;

    for (int k0 = 0; k0 < HH; k0 += 32) {
        __syncthreads();
        // W chunk: rows k0..k0+31 -> 4096 floats = 1024 float4
        {
            const float4* W4 = (const float4*)(W + (size_t)k0 * HH);
            float4* sW4 = (float4*)sW;
            #pragma unroll
            for (int i = 0; i < 4; i++) sW4[tid + i * 256] = W4[tid + i * 256];
        }
        // A chunk transposed: 128 rows x 32 k
        #pragma unroll
        for (int s = 0; s < 16; s++) {
            int idx = tid + s * 256;   // 0..4095
            int kk = idx & 31;
            int r  = idx >> 5;
            int grow = row0 + r;
            sA[kk * 129 + r] = (grow < M) ? A[(size_t)grow * HH + k0 + kk] : 0.0f;
        }
        __syncthreads();
        #pragma unroll
        for (int kk = 0; kk < 32; kk++) {
            float a[8], w[8];
            #pragma unroll
            for (int i = 0; i < 8; i++) a[i] = sA[kk * 129 + ty * 8 + i];
            #pragma unroll
            for (int j = 0; j < 8; j++) w[j] = sW[kk * HH + tx + j * 16];
            #pragma unroll
            for (int i = 0; i < 8; i++)
                #pragma unroll
                for (int j = 0; j < 8; j++) acc[i][j] = fmaf(a[i], w[j], acc[i][j]);
        }
    }

    #pragma unroll
    for (int j = 0; j < 8; j++) {
        int c = tx + j * 16;
        float bb = __ldg(bias + c);
        float s = 1.0f, t = 0.0f;
        if (MODE == 1) {
            float inv = rsqrtf(fabsf(__ldg(bn_v + c)) + 1e-5f);
            s = __ldg(bn_g + c) * inv;
            t = __ldg(bn_b + c) - __ldg(bn_m + c) * s;
        }
        #pragma unroll
        for (int i = 0; i < 8; i++) {
            int r = row0 + ty * 8 + i;
            if (r < M) {
                float z = acc[i][j] + bb;
                if (MODE == 1) z = fmaf(z, s, t);
                C[(size_t)r * HH + c] = fmaxf(z, 0.0f);
            }
        }
    }
}

// ---------------------------------------------------------------------------
__global__ void zero_pool_kernel() {
    int i = blockIdx.x * blockDim.x + threadIdx.x;
    if (i < GG * HH) g_pool[i] = 0.0f;
    if (i < GG) g_cnt[i] = 0.0f;
}

// One warp per node: add h row into pool[batch[i]], count once.
__global__ void pool_kernel(const void* __restrict__ batch_raw, int n) {
    int gt = blockIdx.x * blockDim.x + threadIdx.x;
    int i = gt >> 5;
    if (i >= n) return;
    int lane = gt & 31;
    long long b;
    if (g_idx64) b = __ldg((const long long*)batch_raw + i);
    else         b = __ldg((const int*)batch_raw + i);
    if ((unsigned long long)b >= (unsigned long long)GG) return;  // safety
    int c = lane * 4;
    float4 v = *(const float4*)(g_h + (size_t)i * HH + c);
    float* dp = g_pool + (size_t)b * HH + c;
    atomicAdd(dp + 0, v.x);
    atomicAdd(dp + 1, v.y);
    atomicAdd(dp + 2, v.z);
    atomicAdd(dp + 3, v.w);
    if (lane == 0) atomicAdd(&g_cnt[b], 1.0f);
}

// ---------------------------------------------------------------------------
// Classifier stage 1: g = pool/cnt; st = relu(g @ cls_w1 + b1) -> g_st
__global__ void classifier1_kernel(const float* __restrict__ cls_w1,
                                   const float* __restrict__ cls_b1) {
    __shared__ float sg[GG * HH];   // 32 KB
    int tid = threadIdx.x;          // 256
    for (int i = tid; i < GG * HH; i += 256) {
        float cnt = g_cnt[i >> 7];
        sg[i] = g_pool[i] / fmaxf(cnt, 1.0f);
    }
    __syncthreads();
    for (int e = tid; e < GG * 64; e += 256) {
        int gi = e >> 6;
        int m  = e & 63;
        float s = cls_b1[m];
        #pragma unroll 8
        for (int k = 0; k < HH; k++)
            s = fmaf(sg[gi * HH + k], cls_w1[k * 64 + m], s);
        g_st[e] = fmaxf(s, 0.0f);
    }
}

// Classifier stage 2: out = sigmoid(st @ cls_w2 + b2)
__global__ void classifier2_kernel(const float* __restrict__ cls_w2,
                                   const float* __restrict__ cls_b2,
                                   float* __restrict__ out) {
    int g = threadIdx.x;
    if (g < GG) {
        float s = cls_b2[0];
        #pragma unroll 8
        for (int m = 0; m < 64; m++)
            s = fmaf(g_st[g * 64 + m], cls_w2[m], s);
        out[g] = 1.0f / (1.0f + expf(-s));
    }
}

// ---------------------------------------------------------------------------
extern "C" void kernel_launch(void* const* d_in, const int* in_sizes, int n_in,
                              void* d_out, int out_size) {
    // Resolve input ordering at runtime from element counts.
    // Dict/signature order: in_sizes[1] = edge_index = 3.2M (>1000).
    // Alphabetical order:   in_sizes[1] = bn_beta = 256 (<1000).
    const float *x, *edge_attr, *enc_w, *enc_b, *edge_w, *edge_b, *eps;
    const float *mlp_w1, *mlp_b1, *mlp_w2, *mlp_b2;
    const float *bn_gamma, *bn_beta, *bn_mean, *bn_var;
    const float *cls_w1, *cls_b1, *cls_w2, *cls_b2;
    const void *edge_index, *batch;
    int n, E;

    if (in_sizes[1] > 1000) {
        x          = (const float*)d_in[0];
        edge_index = d_in[1];
        edge_attr  = (const float*)d_in[2];
        batch      = d_in[3];
        enc_w      = (const float*)d_in[4];
        enc_b      = (const float*)d_in[5];
        edge_w     = (const float*)d_in[6];
        edge_b     = (const float*)d_in[7];
        eps        = (const float*)d_in[8];
        mlp_w1     = (const float*)d_in[9];
        mlp_b1     = (const float*)d_in[10];
        mlp_w2     = (const float*)d_in[11];
        mlp_b2     = (const float*)d_in[12];
        bn_gamma   = (const float*)d_in[13];
        bn_beta    = (const float*)d_in[14];
        bn_mean    = (const float*)d_in[15];
        bn_var     = (const float*)d_in[16];
        cls_w1     = (const float*)d_in[17];
        cls_b1     = (const float*)d_in[18];
        cls_w2     = (const float*)d_in[19];
        cls_b2     = (const float*)d_in[20];
        n = in_sizes[0];
        E = in_sizes[2];
    } else {
        // alphabetical: batch, bn_beta, bn_gamma, bn_mean, bn_var, cls_b1,
        // cls_b2, cls_w1, cls_w2, edge_attr, edge_b, edge_index, edge_w,
        // enc_b, enc_w, eps, mlp_b1, mlp_b2, mlp_w1, mlp_w2, x
        batch      = d_in[0];
        bn_beta    = (const float*)d_in[1];
        bn_gamma   = (const float*)d_in[2];
        bn_mean    = (const float*)d_in[3];
        bn_var     = (const float*)d_in[4];
        cls_b1     = (const float*)d_in[5];
        cls_b2     = (const float*)d_in[6];
        cls_w1     = (const float*)d_in[7];
        cls_w2     = (const float*)d_in[8];
        edge_attr  = (const float*)d_in[9];
        edge_b     = (const float*)d_in[10];
        edge_index = d_in[11];
        edge_w     = (const float*)d_in[12];
        enc_b      = (const float*)d_in[13];
        enc_w      = (const float*)d_in[14];
        eps        = (const float*)d_in[15];
        mlp_b1     = (const float*)d_in[16];
        mlp_b2     = (const float*)d_in[17];
        mlp_w1     = (const float*)d_in[18];
        mlp_w2     = (const float*)d_in[19];
        x          = (const float*)d_in[20];
        n = in_sizes[20];
        E = in_sizes[9];
    }
    float* out = (float*)d_out;

    // 0) dtype detect (int32 vs int64 indices)
    detect_kernel<<<1, 32>>>(edge_index, n);

    // 1) encode
    {
        int th = n * 32;
        encode_kernel<<<(th + 255) / 256, 256>>>(x, enc_w, enc_b, n);
    }

    // 2) layers
    int gemm_blocks = (n + 127) / 128;
    for (int l = 0; l < LL; l++) {
        {
            int th = n * 32;
            init_aggr_kernel<<<(th + 255) / 256, 256>>>(eps + l, n);
        }
        {
            long long th = (long long)E * 32;
            scatter_kernel<<<(unsigned)((th + 255) / 256), 256>>>(
                edge_index, edge_attr, edge_w, edge_b, E, n);
        }
        gemm128_kernel<0, BUF_AGGR, BUF_TMP><<<gemm_blocks, 256>>>(
            mlp_w1 + (size_t)l * HH * HH, mlp_b1 + (size_t)l * HH,
            nullptr, nullptr, nullptr, nullptr, n);
        gemm128_kernel<1, BUF_TMP, BUF_H><<<gemm_blocks, 256>>>(
            mlp_w2 + (size_t)l * HH * HH, mlp_b2 + (size_t)l * HH,
            bn_gamma + (size_t)l * HH, bn_beta + (size_t)l * HH,
            bn_mean + (size_t)l * HH, bn_var + (size_t)l * HH, n);
    }

    // 3) global mean pool + classifier
    zero_pool_kernel<<<(GG * HH + 255) / 256, 256>>>();
    {
        int th = n * 32;
        pool_kernel<<<(th + 255) / 256, 256>>>(batch, n);
    }
    classifier1_kernel<<<1, 256>>>(cls_w1, cls_b1);
    classifier2_kernel<<<1, 64>>>(cls_w2, cls_b2, out);
}

// round 4
// speedup vs baseline: 1.7553x; 1.7553x over previous
#include <cuda_runtime.h>
#include <math.h>

// Fixed problem shape
#define HH 128
#define GG 64
#define LL 2
#define NN_MAX 100000

// Scratch: __device__ globals, referenced ONLY inside device code.
__device__ float g_h[NN_MAX * HH];
__device__ float g_aggr[NN_MAX * HH];
__device__ float g_tmp[NN_MAX * HH];
__device__ float g_pool[GG * HH];
__device__ float g_cnt[GG];
__device__ float g_st[GG * 64];
__device__ int   g_idx64;   // 1 if edge_index/batch are int64, 0 if int32

// Buffer selectors for the GEMM template
#define BUF_AGGR 0
#define BUF_TMP  1
#define BUF_H    2

__device__ __forceinline__ float* buf_ptr(int sel) {
    return sel == BUF_AGGR ? g_aggr : (sel == BUF_TMP ? g_tmp : g_h);
}

__device__ __forceinline__ void red_add_v4(float* p, float4 v) {
    asm volatile("red.global.add.v4.f32 [%0], {%1,%2,%3,%4};"
                 :: "l"(p), "f"(v.x), "f"(v.y), "f"(v.z), "f"(v.w)
                 : "memory");
}

// ---------------------------------------------------------------------------
// dtype detect: if data is really int32, reinterpreted int64 slots combine two
// random indices -> some value >= n with overwhelming probability.
__global__ void detect_kernel(const void* ei_raw, int n) {
    if (threadIdx.x == 0 && blockIdx.x == 0) {
        const long long* p = (const long long*)ei_raw;
        int ok = 1;
        for (int i = 0; i < 16; i++) {
            long long v = p[i];
            if (v < 0 || v >= (long long)n) ok = 0;
        }
        g_idx64 = ok;
    }
}

// ---------------------------------------------------------------------------
// h = x @ enc_w + enc_b (rank-1); also writes g_aggr = (1+eps[0])*h (fused).
__global__ void encode_kernel(const float* __restrict__ x,
                              const float* __restrict__ enc_w,
                              const float* __restrict__ enc_b,
                              const float* __restrict__ eps0, int n) {
    int idx = blockIdx.x * blockDim.x + threadIdx.x;   // n*32 threads
    if (idx >= n * 32) return;
    int i = idx >> 5;
    int c = (idx & 31) * 4;
    float xv = __ldg(x + i);
    float s = 1.0f + __ldg(eps0);
    float4 w = *(const float4*)(enc_w + c);
    float4 b = *(const float4*)(enc_b + c);
    float4 r;
    r.x = fmaf(xv, w.x, b.x);
    r.y = fmaf(xv, w.y, b.y);
    r.z = fmaf(xv, w.z, b.z);
    r.w = fmaf(xv, w.w, b.w);
    *(float4*)(g_h + (size_t)i * HH + c) = r;
    float4 a;
    a.x = r.x * s; a.y = r.y * s; a.z = r.z * s; a.w = r.w * s;
    *(float4*)(g_aggr + (size_t)i * HH + c) = a;
}

// ---------------------------------------------------------------------------
// One warp per edge: msg = relu(h[src] + edge_attr*edge_w + edge_b),
// one red.v4 per lane into aggr[dst].
__global__ void scatter_kernel(const void* __restrict__ ei_raw,
                               const float* __restrict__ edge_attr,
                               const float* __restrict__ edge_w,
                               const float* __restrict__ edge_b,
                               int E, int n) {
    int gt = blockIdx.x * blockDim.x + threadIdx.x;
    int e = gt >> 5;
    if (e >= E) return;
    int lane = gt & 31;
    long long src, dst;
    if (g_idx64) {
        const long long* ei = (const long long*)ei_raw;
        src = __ldg(ei + e);
        dst = __ldg(ei + E + e);
    } else {
        const int* ei = (const int*)ei_raw;
        src = __ldg(ei + e);
        dst = __ldg(ei + E + e);
    }
    if ((unsigned long long)src >= (unsigned long long)n ||
        (unsigned long long)dst >= (unsigned long long)n) return;  // safety
    float ea = __ldg(edge_attr + e);
    int c = lane * 4;
    float4 hv = *(const float4*)(g_h + (size_t)src * HH + c);
    float4 ew = *(const float4*)(edge_w + c);
    float4 eb = *(const float4*)(edge_b + c);
    float4 m;
    m.x = fmaxf(hv.x + fmaf(ea, ew.x, eb.x), 0.0f);
    m.y = fmaxf(hv.y + fmaf(ea, ew.y, eb.y), 0.0f);
    m.z = fmaxf(hv.z + fmaf(ea, ew.z, eb.z), 0.0f);
    m.w = fmaxf(hv.w + fmaf(ea, ew.w, eb.w), 0.0f);
    red_add_v4(g_aggr + (size_t)dst * HH + c, m);
}

// ---------------------------------------------------------------------------
// C[M,128] = act(A[M,128] @ W[128,128] + bias), optional BN epilogue.
// MODE 0: bias+relu -> DST.
// MODE 1: bias+BN+relu -> DST.  If FUSE_AGGR: also g_aggr = (1+eps_next)*result.
// 256 threads, 128x128 tile, 8x8/thread, BK=32, 2 CTAs/SM.
template <int MODE, int SRC, int DST, int FUSE_AGGR>
__global__ void __launch_bounds__(256, 2)
gemm128_kernel(const float* __restrict__ W,
               const float* __restrict__ bias,
               const float* __restrict__ bn_g,
               const float* __restrict__ bn_b,
               const float* __restrict__ bn_m,
               const float* __restrict__ bn_v,
               const float* __restrict__ eps_next,
               int M) {
    const float* A = buf_ptr(SRC);
    float*       C = buf_ptr(DST);

    __shared__ float sW[32 * HH];    // sW[kk*128 + c]
    __shared__ float sA[32 * 129];   // sA[kk*129 + r]
    int tid = threadIdx.x;           // 256
    int tx = tid & 15;               // cols: tx + 16*j
    int ty = tid >> 4;               // rows: ty*8 + i
    int row0 = blockIdx.x * 128;

    float acc[8][8];
    #pragma unroll
    for (int i = 0; i < 8; i++)
        #pragma unroll
        for (int j = 0; j < 8; j++) acc[i][j] = 0.0f;

    for (int k0 = 0; k0 < HH; k0 += 32) {
        __syncthreads();
        {
            const float4* W4 = (const float4*)(W + (size_t)k0 * HH);
            float4* sW4 = (float4*)sW;
            #pragma unroll
            for (int i = 0; i < 4; i++) sW4[tid + i * 256] = W4[tid + i * 256];
        }
        #pragma unroll
        for (int s = 0; s < 16; s++) {
            int idx = tid + s * 256;   // 0..4095
            int kk = idx & 31;
            int r  = idx >> 5;
            int grow = row0 + r;
            sA[kk * 129 + r] = (grow < M) ? A[(size_t)grow * HH + k0 + kk] : 0.0f;
        }
        __syncthreads();
        #pragma unroll
        for (int kk = 0; kk < 32; kk++) {
            float a[8], w[8];
            #pragma unroll
            for (int i = 0; i < 8; i++) a[i] = sA[kk * 129 + ty * 8 + i];
            #pragma unroll
            for (int j = 0; j < 8; j++) w[j] = sW[kk * HH + tx + j * 16];
            #pragma unroll
            for (int i = 0; i < 8; i++)
                #pragma unroll
                for (int j = 0; j < 8; j++) acc[i][j] = fmaf(a[i], w[j], acc[i][j]);
        }
    }

    float se = 1.0f;
    if (FUSE_AGGR) se = 1.0f + __ldg(eps_next);

    #pragma unroll
    for (int j = 0; j < 8; j++) {
        int c = tx + j * 16;
        float bb = __ldg(bias + c);
        float s = 1.0f, t = 0.0f;
        if (MODE == 1) {
            float inv = rsqrtf(fabsf(__ldg(bn_v + c)) + 1e-5f);
            s = __ldg(bn_g + c) * inv;
            t = __ldg(bn_b + c) - __ldg(bn_m + c) * s;
        }
        #pragma unroll
        for (int i = 0; i < 8; i++) {
            int r = row0 + ty * 8 + i;
            if (r < M) {
                float z = acc[i][j] + bb;
                if (MODE == 1) z = fmaf(z, s, t);
                z = fmaxf(z, 0.0f);
                C[(size_t)r * HH + c] = z;
                if (FUSE_AGGR) g_aggr[(size_t)r * HH + c] = z * se;
            }
        }
    }
}

// ---------------------------------------------------------------------------
__global__ void zero_pool_kernel() {
    int i = blockIdx.x * blockDim.x + threadIdx.x;
    if (i < GG * HH) g_pool[i] = 0.0f;
    if (i < GG) g_cnt[i] = 0.0f;
}

// One warp per node: red.v4 h row into pool[batch[i]], count once.
__global__ void pool_kernel(const void* __restrict__ batch_raw, int n) {
    int gt = blockIdx.x * blockDim.x + threadIdx.x;
    int i = gt >> 5;
    if (i >= n) return;
    int lane = gt & 31;
    long long b;
    if (g_idx64) b = __ldg((const long long*)batch_raw + i);
    else         b = __ldg((const int*)batch_raw + i);
    if ((unsigned long long)b >= (unsigned long long)GG) return;  // safety
    int c = lane * 4;
    float4 v = *(const float4*)(g_h + (size_t)i * HH + c);
    red_add_v4(g_pool + (size_t)b * HH + c, v);
    if (lane == 0) atomicAdd(&g_cnt[b], 1.0f);
}

// ---------------------------------------------------------------------------
// Classifier stage 1: g = pool/cnt; st = relu(g @ cls_w1 + b1) -> g_st
__global__ void classifier1_kernel(const float* __restrict__ cls_w1,
                                   const float* __restrict__ cls_b1) {
    __shared__ float sg[GG * HH];   // 32 KB
    int tid = threadIdx.x;          // 256
    for (int i = tid; i < GG * HH; i += 256) {
        float cnt = g_cnt[i >> 7];
        sg[i] = g_pool[i] / fmaxf(cnt, 1.0f);
    }
    __syncthreads();
    for (int e = tid; e < GG * 64; e += 256) {
        int gi = e >> 6;
        int m  = e & 63;
        float s = cls_b1[m];
        #pragma unroll 8
        for (int k = 0; k < HH; k++)
            s = fmaf(sg[gi * HH + k], cls_w1[k * 64 + m], s);
        g_st[e] = fmaxf(s, 0.0f);
    }
}

// Classifier stage 2: out = sigmoid(st @ cls_w2 + b2)
__global__ void classifier2_kernel(const float* __restrict__ cls_w2,
                                   const float* __restrict__ cls_b2,
                                   float* __restrict__ out) {
    int g = threadIdx.x;
    if (g < GG) {
        float s = cls_b2[0];
        #pragma unroll 8
        for (int m = 0; m < 64; m++)
            s = fmaf(g_st[g * 64 + m], cls_w2[m], s);
        out[g] = 1.0f / (1.0f + expf(-s));
    }
}

// ---------------------------------------------------------------------------
extern "C" void kernel_launch(void* const* d_in, const int* in_sizes, int n_in,
                              void* d_out, int out_size) {
    const float *x, *edge_attr, *enc_w, *enc_b, *edge_w, *edge_b, *eps;
    const float *mlp_w1, *mlp_b1, *mlp_w2, *mlp_b2;
    const float *bn_gamma, *bn_beta, *bn_mean, *bn_var;
    const float *cls_w1, *cls_b1, *cls_w2, *cls_b2;
    const void *edge_index, *batch;
    int n, E;

    if (in_sizes[1] > 1000) {
        // dict / reference-signature order
        x          = (const float*)d_in[0];
        edge_index = d_in[1];
        edge_attr  = (const float*)d_in[2];
        batch      = d_in[3];
        enc_w      = (const float*)d_in[4];
        enc_b      = (const float*)d_in[5];
        edge_w     = (const float*)d_in[6];
        edge_b     = (const float*)d_in[7];
        eps        = (const float*)d_in[8];
        mlp_w1     = (const float*)d_in[9];
        mlp_b1     = (const float*)d_in[10];
        mlp_w2     = (const float*)d_in[11];
        mlp_b2     = (const float*)d_in[12];
        bn_gamma   = (const float*)d_in[13];
        bn_beta    = (const float*)d_in[14];
        bn_mean    = (const float*)d_in[15];
        bn_var     = (const float*)d_in[16];
        cls_w1     = (const float*)d_in[17];
        cls_b1     = (const float*)d_in[18];
        cls_w2     = (const float*)d_in[19];
        cls_b2     = (const float*)d_in[20];
        n = in_sizes[0];
        E = in_sizes[2];
    } else {
        // alphabetical order
        batch      = d_in[0];
        bn_beta    = (const float*)d_in[1];
        bn_gamma   = (const float*)d_in[2];
        bn_mean    = (const float*)d_in[3];
        bn_var     = (const float*)d_in[4];
        cls_b1     = (const float*)d_in[5];
        cls_b2     = (const float*)d_in[6];
        cls_w1     = (const float*)d_in[7];
        cls_w2     = (const float*)d_in[8];
        edge_attr  = (const float*)d_in[9];
        edge_b     = (const float*)d_in[10];
        edge_index = d_in[11];
        edge_w     = (const float*)d_in[12];
        enc_b      = (const float*)d_in[13];
        enc_w      = (const float*)d_in[14];
        eps        = (const float*)d_in[15];
        mlp_b1     = (const float*)d_in[16];
        mlp_b2     = (const float*)d_in[17];
        mlp_w1     = (const float*)d_in[18];
        mlp_w2     = (const float*)d_in[19];
        x          = (const float*)d_in[20];
        n = in_sizes[20];
        E = in_sizes[9];
    }
    float* out = (float*)d_out;

    // 0) dtype detect
    detect_kernel<<<1, 32>>>(edge_index, n);

    // 1) encode (+ fused aggr init for layer 0)
    {
        int th = n * 32;
        encode_kernel<<<(th + 255) / 256, 256>>>(x, enc_w, enc_b, eps, n);
    }

    // 2) layers
    int gemm_blocks = (n + 127) / 128;
    long long sth = (long long)E * 32;
    unsigned sgrid = (unsigned)((sth + 255) / 256);

    // layer 0
    scatter_kernel<<<sgrid, 256>>>(edge_index, edge_attr, edge_w, edge_b, E, n);
    gemm128_kernel<0, BUF_AGGR, BUF_TMP, 0><<<gemm_blocks, 256>>>(
        mlp_w1, mlp_b1, nullptr, nullptr, nullptr, nullptr, nullptr, n);
    gemm128_kernel<1, BUF_TMP, BUF_H, 1><<<gemm_blocks, 256>>>(
        mlp_w2, mlp_b2, bn_gamma, bn_beta, bn_mean, bn_var, eps + 1, n);

    // layer 1
    scatter_kernel<<<sgrid, 256>>>(edge_index, edge_attr, edge_w, edge_b, E, n);
    gemm128_kernel<0, BUF_AGGR, BUF_TMP, 0><<<gemm_blocks, 256>>>(
        mlp_w1 + (size_t)HH * HH, mlp_b1 + HH,
        nullptr, nullptr, nullptr, nullptr, nullptr, n);
    gemm128_kernel<1, BUF_TMP, BUF_H, 0><<<gemm_blocks, 256>>>(
        mlp_w2 + (size_t)HH * HH, mlp_b2 + HH,
        bn_gamma + HH, bn_beta + HH, bn_mean + HH, bn_var + HH, nullptr, n);

    // 3) global mean pool + classifier
    zero_pool_kernel<<<(GG * HH + 255) / 256, 256>>>();
    {
        int th = n * 32;
        pool_kernel<<<(th + 255) / 256, 256>>>(batch, n);
    }
    classifier1_kernel<<<1, 256>>>(cls_w1, cls_b1);
    classifier2_kernel<<<1, 64>>>(cls_w2, cls_b2, out);
}

// round 5
// speedup vs baseline: 1.8134x; 1.0331x over previous
#include <cuda_runtime.h>
#include <math.h>

// Fixed problem shape
#define HH 128
#define GG 64
#define LL 2
#define NN_MAX 100000

typedef unsigned long long u64;

// Scratch: __device__ globals, referenced ONLY inside device code.
__device__ float g_h[NN_MAX * HH];
__device__ float g_aggr[NN_MAX * HH];
__device__ float g_tmp[NN_MAX * HH];
__device__ float g_pool[GG * HH];
__device__ float g_cnt[GG];
__device__ float g_st[GG * 64];
__device__ int   g_idx64;   // 1 if edge_index/batch are int64, 0 if int32

// Buffer selectors for the GEMM template
#define BUF_AGGR 0
#define BUF_TMP  1
#define BUF_H    2

__device__ __forceinline__ float* buf_ptr(int sel) {
    return sel == BUF_AGGR ? g_aggr : (sel == BUF_TMP ? g_tmp : g_h);
}

__device__ __forceinline__ void red_add_v4(float* p, float4 v) {
    asm volatile("red.global.add.v4.f32 [%0], {%1,%2,%3,%4};"
                 :: "l"(p), "f"(v.x), "f"(v.y), "f"(v.z), "f"(v.w)
                 : "memory");
}

// ---- packed f32x2 helpers (FFMA2 — ptxas never auto-generates this) ------
__device__ __forceinline__ u64 dup2(float v) {
    u64 r; asm("mov.b64 %0, {%1,%2};" : "=l"(r) : "f"(v), "f"(v)); return r;
}
__device__ __forceinline__ void fma2(u64& d, u64 a, u64 b) {
    asm("fma.rn.f32x2 %0, %1, %2, %0;" : "+l"(d) : "l"(a), "l"(b));
}
__device__ __forceinline__ float2 unpack2(u64 v) {
    float2 r; asm("mov.b64 {%0,%1}, %2;" : "=f"(r.x), "=f"(r.y) : "l"(v));
    return r;
}

// ---------------------------------------------------------------------------
// dtype detect: if data is really int32, reinterpreted int64 slots combine two
// random indices -> some value >= n with overwhelming probability.
__global__ void detect_kernel(const void* ei_raw, int n) {
    if (threadIdx.x == 0 && blockIdx.x == 0) {
        const long long* p = (const long long*)ei_raw;
        int ok = 1;
        for (int i = 0; i < 16; i++) {
            long long v = p[i];
            if (v < 0 || v >= (long long)n) ok = 0;
        }
        g_idx64 = ok;
    }
}

// ---------------------------------------------------------------------------
// h = x @ enc_w + enc_b (rank-1); also writes g_aggr = (1+eps[0])*h (fused).
__global__ void encode_kernel(const float* __restrict__ x,
                              const float* __restrict__ enc_w,
                              const float* __restrict__ enc_b,
                              const float* __restrict__ eps0, int n) {
    int idx = blockIdx.x * blockDim.x + threadIdx.x;   // n*32 threads
    if (idx >= n * 32) return;
    int i = idx >> 5;
    int c = (idx & 31) * 4;
    float xv = __ldg(x + i);
    float s = 1.0f + __ldg(eps0);
    float4 w = *(const float4*)(enc_w + c);
    float4 b = *(const float4*)(enc_b + c);
    float4 r;
    r.x = fmaf(xv, w.x, b.x);
    r.y = fmaf(xv, w.y, b.y);
    r.z = fmaf(xv, w.z, b.z);
    r.w = fmaf(xv, w.w, b.w);
    *(float4*)(g_h + (size_t)i * HH + c) = r;
    float4 a;
    a.x = r.x * s; a.y = r.y * s; a.z = r.z * s; a.w = r.w * s;
    *(float4*)(g_aggr + (size_t)i * HH + c) = a;
}

// ---------------------------------------------------------------------------
// One warp per edge: msg = relu(h[src] + edge_attr*edge_w + edge_b),
// one red.v4 per lane into aggr[dst].
__global__ void scatter_kernel(const void* __restrict__ ei_raw,
                               const float* __restrict__ edge_attr,
                               const float* __restrict__ edge_w,
                               const float* __restrict__ edge_b,
                               int E, int n) {
    int gt = blockIdx.x * blockDim.x + threadIdx.x;
    int e = gt >> 5;
    if (e >= E) return;
    int lane = gt & 31;
    long long src, dst;
    if (g_idx64) {
        const long long* ei = (const long long*)ei_raw;
        src = __ldg(ei + e);
        dst = __ldg(ei + E + e);
    } else {
        const int* ei = (const int*)ei_raw;
        src = __ldg(ei + e);
        dst = __ldg(ei + E + e);
    }
    if ((unsigned long long)src >= (unsigned long long)n ||
        (unsigned long long)dst >= (unsigned long long)n) return;  // safety
    float ea = __ldg(edge_attr + e);
    int c = lane * 4;
    float4 hv = *(const float4*)(g_h + (size_t)src * HH + c);
    float4 ew = *(const float4*)(edge_w + c);
    float4 eb = *(const float4*)(edge_b + c);
    float4 m;
    m.x = fmaxf(hv.x + fmaf(ea, ew.x, eb.x), 0.0f);
    m.y = fmaxf(hv.y + fmaf(ea, ew.y, eb.y), 0.0f);
    m.z = fmaxf(hv.z + fmaf(ea, ew.z, eb.z), 0.0f);
    m.w = fmaxf(hv.w + fmaf(ea, ew.w, eb.w), 0.0f);
    red_add_v4(g_aggr + (size_t)dst * HH + c, m);
}

// ---------------------------------------------------------------------------
// C[M,128] = act(A[M,128] @ W[128,128] + bias), optional BN epilogue.
// FFMA2 (f32x2) inner loop: accumulators packed along rows (pairs), doubling
// fp32 FMA throughput vs scalar FFMA (rt_SMSP 2 -> effective 1).
// Thread (tx,ty): rows ty*8..+7 (4 packed pairs), cols tx*8..+7.
// MODE 0: bias+relu. MODE 1: bias+BN+relu. FUSE_AGGR: also aggr = (1+eps)*res.
#define SA_STRIDE 130   // even -> u64-aligned row pairs; 2-way STS conflict only
template <int MODE, int SRC, int DST, int FUSE_AGGR>
__global__ void __launch_bounds__(256, 2)
gemm128_kernel(const float* __restrict__ W,
               const float* __restrict__ bias,
               const float* __restrict__ bn_g,
               const float* __restrict__ bn_b,
               const float* __restrict__ bn_m,
               const float* __restrict__ bn_v,
               const float* __restrict__ eps_next,
               int M) {
    const float* A = buf_ptr(SRC);
    float*       C = buf_ptr(DST);

    __shared__ float sW[32 * HH];          // sW[kk*128 + c]
    __shared__ float sA[32 * SA_STRIDE];   // sA[kk*SA_STRIDE + r]
    int tid = threadIdx.x;           // 256
    int tx = tid & 15;               // cols: tx*8 .. tx*8+7
    int ty = tid >> 4;               // rows: ty*8 .. ty*8+7
    int row0 = blockIdx.x * 128;

    u64 acc[4][8];                   // [row-pair][col]
    #pragma unroll
    for (int i = 0; i < 4; i++)
        #pragma unroll
        for (int j = 0; j < 8; j++) acc[i][j] = 0ull;

    for (int k0 = 0; k0 < HH; k0 += 32) {
        __syncthreads();
        {
            const float4* W4 = (const float4*)(W + (size_t)k0 * HH);
            float4* sW4 = (float4*)sW;
            #pragma unroll
            for (int i = 0; i < 4; i++) sW4[tid + i * 256] = W4[tid + i * 256];
        }
        #pragma unroll
        for (int s = 0; s < 16; s++) {
            int idx = tid + s * 256;   // 0..4095
            int kk = idx & 31;
            int r  = idx >> 5;
            int grow = row0 + r;
            sA[kk * SA_STRIDE + r] =
                (grow < M) ? A[(size_t)grow * HH + k0 + kk] : 0.0f;
        }
        __syncthreads();
        #pragma unroll
        for (int kk = 0; kk < 32; kk++) {
            // a: 4 packed row-pairs, direct u64 loads (8B aligned)
            const u64* ap = (const u64*)(sA + kk * SA_STRIDE + ty * 8);
            u64 a2[4];
            #pragma unroll
            for (int i = 0; i < 4; i++) a2[i] = ap[i];
            // w: 8 cols, duplicated into pairs
            float4 w0 = *(const float4*)(sW + kk * HH + tx * 8);
            float4 w1 = *(const float4*)(sW + kk * HH + tx * 8 + 4);
            u64 wd[8];
            wd[0] = dup2(w0.x); wd[1] = dup2(w0.y);
            wd[2] = dup2(w0.z); wd[3] = dup2(w0.w);
            wd[4] = dup2(w1.x); wd[5] = dup2(w1.y);
            wd[6] = dup2(w1.z); wd[7] = dup2(w1.w);
            #pragma unroll
            for (int i = 0; i < 4; i++)
                #pragma unroll
                for (int j = 0; j < 8; j++) fma2(acc[i][j], a2[i], wd[j]);
        }
    }

    float se = 1.0f;
    if (FUSE_AGGR) se = 1.0f + __ldg(eps_next);

    float sb[8], ss[8], stt[8];
    #pragma unroll
    for (int j = 0; j < 8; j++) {
        int c = tx * 8 + j;
        sb[j] = __ldg(bias + c);
        if (MODE == 1) {
            float inv = rsqrtf(fabsf(__ldg(bn_v + c)) + 1e-5f);
            ss[j]  = __ldg(bn_g + c) * inv;
            stt[j] = __ldg(bn_b + c) - __ldg(bn_m + c) * ss[j];
        }
    }

    #pragma unroll
    for (int i = 0; i < 8; i++) {
        int r = row0 + ty * 8 + i;
        if (r < M) {
            float v[8];
            #pragma unroll
            for (int j = 0; j < 8; j++) {
                float2 p = unpack2(acc[i >> 1][j]);
                float z = ((i & 1) ? p.y : p.x) + sb[j];
                if (MODE == 1) z = fmaf(z, ss[j], stt[j]);
                v[j] = fmaxf(z, 0.0f);
            }
            float4* cp = (float4*)(C + (size_t)r * HH + tx * 8);
            cp[0] = make_float4(v[0], v[1], v[2], v[3]);
            cp[1] = make_float4(v[4], v[5], v[6], v[7]);
            if (FUSE_AGGR) {
                float4* apx = (float4*)(g_aggr + (size_t)r * HH + tx * 8);
                apx[0] = make_float4(v[0] * se, v[1] * se, v[2] * se, v[3] * se);
                apx[1] = make_float4(v[4] * se, v[5] * se, v[6] * se, v[7] * se);
            }
        }
    }
}

// ---------------------------------------------------------------------------
__global__ void zero_pool_kernel() {
    int i = blockIdx.x * blockDim.x + threadIdx.x;
    if (i < GG * HH) g_pool[i] = 0.0f;
    if (i < GG) g_cnt[i] = 0.0f;
}

// One warp per node: red.v4 h row into pool[batch[i]], count once.
__global__ void pool_kernel(const void* __restrict__ batch_raw, int n) {
    int gt = blockIdx.x * blockDim.x + threadIdx.x;
    int i = gt >> 5;
    if (i >= n) return;
    int lane = gt & 31;
    long long b;
    if (g_idx64) b = __ldg((const long long*)batch_raw + i);
    else         b = __ldg((const int*)batch_raw + i);
    if ((unsigned long long)b >= (unsigned long long)GG) return;  // safety
    int c = lane * 4;
    float4 v = *(const float4*)(g_h + (size_t)i * HH + c);
    red_add_v4(g_pool + (size_t)b * HH + c, v);
    if (lane == 0) atomicAdd(&g_cnt[b], 1.0f);
}

// ---------------------------------------------------------------------------
// Classifier stage 1: g = pool/cnt; st = relu(g @ cls_w1 + b1) -> g_st
__global__ void classifier1_kernel(const float* __restrict__ cls_w1,
                                   const float* __restrict__ cls_b1) {
    __shared__ float sg[GG * HH];   // 32 KB
    int tid = threadIdx.x;          // 256
    for (int i = tid; i < GG * HH; i += 256) {
        float cnt = g_cnt[i >> 7];
        sg[i] = g_pool[i] / fmaxf(cnt, 1.0f);
    }
    __syncthreads();
    for (int e = tid; e < GG * 64; e += 256) {
        int gi = e >> 6;
        int m  = e & 63;
        float s = cls_b1[m];
        #pragma unroll 8
        for (int k = 0; k < HH; k++)
            s = fmaf(sg[gi * HH + k], cls_w1[k * 64 + m], s);
        g_st[e] = fmaxf(s, 0.0f);
    }
}

// Classifier stage 2: out = sigmoid(st @ cls_w2 + b2)
__global__ void classifier2_kernel(const float* __restrict__ cls_w2,
                                   const float* __restrict__ cls_b2,
                                   float* __restrict__ out) {
    int g = threadIdx.x;
    if (g < GG) {
        float s = cls_b2[0];
        #pragma unroll 8
        for (int m = 0; m < 64; m++)
            s = fmaf(g_st[g * 64 + m], cls_w2[m], s);
        out[g] = 1.0f / (1.0f + expf(-s));
    }
}

// ---------------------------------------------------------------------------
extern "C" void kernel_launch(void* const* d_in, const int* in_sizes, int n_in,
                              void* d_out, int out_size) {
    const float *x, *edge_attr, *enc_w, *enc_b, *edge_w, *edge_b, *eps;
    const float *mlp_w1, *mlp_b1, *mlp_w2, *mlp_b2;
    const float *bn_gamma, *bn_beta, *bn_mean, *bn_var;
    const float *cls_w1, *cls_b1, *cls_w2, *cls_b2;
    const void *edge_index, *batch;
    int n, E;

    if (in_sizes[1] > 1000) {
        // dict / reference-signature order
        x          = (const float*)d_in[0];
        edge_index = d_in[1];
        edge_attr  = (const float*)d_in[2];
        batch      = d_in[3];
        enc_w      = (const float*)d_in[4];
        enc_b      = (const float*)d_in[5];
        edge_w     = (const float*)d_in[6];
        edge_b     = (const float*)d_in[7];
        eps        = (const float*)d_in[8];
        mlp_w1     = (const float*)d_in[9];
        mlp_b1     = (const float*)d_in[10];
        mlp_w2     = (const float*)d_in[11];
        mlp_b2     = (const float*)d_in[12];
        bn_gamma   = (const float*)d_in[13];
        bn_beta    = (const float*)d_in[14];
        bn_mean    = (const float*)d_in[15];
        bn_var     = (const float*)d_in[16];
        cls_w1     = (const float*)d_in[17];
        cls_b1     = (const float*)d_in[18];
        cls_w2     = (const float*)d_in[19];
        cls_b2     = (const float*)d_in[20];
        n = in_sizes[0];
        E = in_sizes[2];
    } else {
        // alphabetical order
        batch      = d_in[0];
        bn_beta    = (const float*)d_in[1];
        bn_gamma   = (const float*)d_in[2];
        bn_mean    = (const float*)d_in[3];
        bn_var     = (const float*)d_in[4];
        cls_b1     = (const float*)d_in[5];
        cls_b2     = (const float*)d_in[6];
        cls_w1     = (const float*)d_in[7];
        cls_w2     = (const float*)d_in[8];
        edge_attr  = (const float*)d_in[9];
        edge_b     = (const float*)d_in[10];
        edge_index = d_in[11];
        edge_w     = (const float*)d_in[12];
        enc_b      = (const float*)d_in[13];
        enc_w      = (const float*)d_in[14];
        eps        = (const float*)d_in[15];
        mlp_b1     = (const float*)d_in[16];
        mlp_b2     = (const float*)d_in[17];
        mlp_w1     = (const float*)d_in[18];
        mlp_w2     = (const float*)d_in[19];
        x          = (const float*)d_in[20];
        n = in_sizes[20];
        E = in_sizes[9];
    }
    float* out = (float*)d_out;

    // 0) dtype detect
    detect_kernel<<<1, 32>>>(edge_index, n);

    // 1) encode (+ fused aggr init for layer 0)
    {
        int th = n * 32;
        encode_kernel<<<(th + 255) / 256, 256>>>(x, enc_w, enc_b, eps, n);
    }

    // 2) layers
    int gemm_blocks = (n + 127) / 128;
    long long sth = (long long)E * 32;
    unsigned sgrid = (unsigned)((sth + 255) / 256);

    // layer 0
    scatter_kernel<<<sgrid, 256>>>(edge_index, edge_attr, edge_w, edge_b, E, n);
    gemm128_kernel<0, BUF_AGGR, BUF_TMP, 0><<<gemm_blocks, 256>>>(
        mlp_w1, mlp_b1, nullptr, nullptr, nullptr, nullptr, nullptr, n);
    gemm128_kernel<1, BUF_TMP, BUF_H, 1><<<gemm_blocks, 256>>>(
        mlp_w2, mlp_b2, bn_gamma, bn_beta, bn_mean, bn_var, eps + 1, n);

    // layer 1
    scatter_kernel<<<sgrid, 256>>>(edge_index, edge_attr, edge_w, edge_b, E, n);
    gemm128_kernel<0, BUF_AGGR, BUF_TMP, 0><<<gemm_blocks, 256>>>(
        mlp_w1 + (size_t)HH * HH, mlp_b1 + HH,
        nullptr, nullptr, nullptr, nullptr, nullptr, n);
    gemm128_kernel<1, BUF_TMP, BUF_H, 0><<<gemm_blocks, 256>>>(
        mlp_w2 + (size_t)HH * HH, mlp_b2 + HH,
        bn_gamma + HH, bn_beta + HH, bn_mean + HH, bn_var + HH, nullptr, n);

    // 3) global mean pool + classifier
    zero_pool_kernel<<<(GG * HH + 255) / 256, 256>>>();
    {
        int th = n * 32;
        pool_kernel<<<(th + 255) / 256, 256>>>(batch, n);
    }
    classifier1_kernel<<<1, 256>>>(cls_w1, cls_b1);
    classifier2_kernel<<<1, 64>>>(cls_w2, cls_b2, out);
}

// round 6
// speedup vs baseline: 2.5488x; 1.4056x over previous
#include <cuda_runtime.h>
#include <math.h>

// Fixed problem shape
#define HH 128
#define GG 64
#define LL 2
#define NN_MAX 100000
#define EE_MAX 1600000
#define NBLK ((NN_MAX + 255) / 256)   // 391

typedef unsigned long long u64;

// Scratch: __device__ globals, referenced ONLY inside device code.
__device__ float g_h[NN_MAX * HH];
__device__ float g_aggr[NN_MAX * HH];
__device__ float g_tmp[NN_MAX * HH];
__device__ float g_pool[GG * HH];
__device__ float g_cnt[GG];
__device__ float g_st[GG * 64];
__device__ int   g_idx64;           // 1 if edge_index/batch are int64

// CSR scratch (built once per call; graph shared by both layers)
__device__ int   g_deg[NN_MAX];
__device__ int   g_rowptr[NN_MAX + 1];
__device__ int   g_cursor[NN_MAX];
__device__ int   g_bsum[512];
__device__ int   g_boff[512];
__device__ int   g_esrc[EE_MAX];    // src node per edge, sorted by dst
__device__ float g_eea[EE_MAX];     // edge_attr per edge, sorted by dst

// Buffer selectors for the GEMM template
#define BUF_AGGR 0
#define BUF_TMP  1
#define BUF_H    2
__device__ __forceinline__ float* buf_ptr(int sel) {
    return sel == BUF_AGGR ? g_aggr : (sel == BUF_TMP ? g_tmp : g_h);
}

__device__ __forceinline__ void red_add_v4(float* p, float4 v) {
    asm volatile("red.global.add.v4.f32 [%0], {%1,%2,%3,%4};"
                 :: "l"(p), "f"(v.x), "f"(v.y), "f"(v.z), "f"(v.w)
                 : "memory");
}

// ---- packed f32x2 helpers (FFMA2 — ptxas never auto-generates this) ------
__device__ __forceinline__ u64 dup2(float v) {
    u64 r; asm("mov.b64 %0, {%1,%2};" : "=l"(r) : "f"(v), "f"(v)); return r;
}
__device__ __forceinline__ void fma2(u64& d, u64 a, u64 b) {
    asm("fma.rn.f32x2 %0, %1, %2, %0;" : "+l"(d) : "l"(a), "l"(b));
}
__device__ __forceinline__ float2 unpack2(u64 v) {
    float2 r; asm("mov.b64 {%0,%1}, %2;" : "=f"(r.x), "=f"(r.y) : "l"(v));
    return r;
}

// ---------------------------------------------------------------------------
__global__ void detect_kernel(const void* ei_raw, int n) {
    if (threadIdx.x == 0 && blockIdx.x == 0) {
        const long long* p = (const long long*)ei_raw;
        int ok = 1;
        for (int i = 0; i < 16; i++) {
            long long v = p[i];
            if (v < 0 || v >= (long long)n) ok = 0;
        }
        g_idx64 = ok;
    }
}

// ---------------------------------------------------------------------------
// h = x @ enc_w + enc_b (rank-1)
__global__ void encode_kernel(const float* __restrict__ x,
                              const float* __restrict__ enc_w,
                              const float* __restrict__ enc_b, int n) {
    int idx = blockIdx.x * blockDim.x + threadIdx.x;
    if (idx >= n * 32) return;
    int i = idx >> 5;
    int c = (idx & 31) * 4;
    float xv = __ldg(x + i);
    float4 w = *(const float4*)(enc_w + c);
    float4 b = *(const float4*)(enc_b + c);
    float4 r;
    r.x = fmaf(xv, w.x, b.x);
    r.y = fmaf(xv, w.y, b.y);
    r.z = fmaf(xv, w.z, b.z);
    r.w = fmaf(xv, w.w, b.w);
    *(float4*)(g_h + (size_t)i * HH + c) = r;
}

// ============================ CSR build (once) =============================
__global__ void zero_deg_kernel(int n) {
    int i = blockIdx.x * blockDim.x + threadIdx.x;
    if (i < n) g_deg[i] = 0;
}

__global__ void csr_count_kernel(const void* __restrict__ ei_raw, int E, int n) {
    int e = blockIdx.x * blockDim.x + threadIdx.x;
    if (e >= E) return;
    long long dst;
    if (g_idx64) dst = __ldg((const long long*)ei_raw + E + e);
    else         dst = __ldg((const int*)ei_raw + E + e);
    if ((unsigned long long)dst >= (unsigned long long)n) return;
    atomicAdd(&g_deg[(int)dst], 1);
}

// per-block sums of degrees (256 per block)
__global__ void blocksum_kernel(int n) {
    __shared__ int s[256];
    int t = threadIdx.x;
    int i = blockIdx.x * 256 + t;
    s[t] = (i < n) ? g_deg[i] : 0;
    __syncthreads();
    for (int d = 128; d > 0; d >>= 1) {
        if (t < d) s[t] += s[t + d];
        __syncthreads();
    }
    if (t == 0) g_bsum[blockIdx.x] = s[0];
}

// single-block exclusive scan of block sums (nb <= 512)
__global__ void scan_bsum_kernel(int nb) {
    __shared__ int s[512];
    int t = threadIdx.x;
    int v0 = (t < nb) ? g_bsum[t] : 0;
    s[t] = v0;
    __syncthreads();
    for (int d = 1; d < 512; d <<= 1) {
        int v = (t >= d) ? s[t - d] : 0;
        __syncthreads();
        s[t] += v;
        __syncthreads();
    }
    g_boff[t] = s[t] - v0;   // exclusive
}

// per-block scan -> row_ptr (exclusive) and cursor init; row_ptr[n] = E
__global__ void rowptr_kernel(int n, int E) {
    __shared__ int s[256];
    int t = threadIdx.x;
    int i = blockIdx.x * 256 + t;
    int d = (i < n) ? g_deg[i] : 0;
    s[t] = d;
    __syncthreads();
    for (int dd = 1; dd < 256; dd <<= 1) {
        int v = (t >= dd) ? s[t - dd] : 0;
        __syncthreads();
        s[t] += v;
        __syncthreads();
    }
    int excl = s[t] - d + g_boff[blockIdx.x];
    if (i < n) {
        g_rowptr[i] = excl;
        g_cursor[i] = excl;
        if (i == n - 1) g_rowptr[n] = E;
    }
}

// fill dst-sorted src / edge_attr arrays
__global__ void csr_fill_kernel(const void* __restrict__ ei_raw,
                                const float* __restrict__ edge_attr,
                                int E, int n) {
    int e = blockIdx.x * blockDim.x + threadIdx.x;
    if (e >= E) return;
    long long src, dst;
    if (g_idx64) {
        const long long* ei = (const long long*)ei_raw;
        src = __ldg(ei + e);
        dst = __ldg(ei + E + e);
    } else {
        const int* ei = (const int*)ei_raw;
        src = __ldg(ei + e);
        dst = __ldg(ei + E + e);
    }
    if ((unsigned long long)src >= (unsigned long long)n ||
        (unsigned long long)dst >= (unsigned long long)n) return;
    int pos = atomicAdd(&g_cursor[(int)dst], 1);
    g_esrc[pos] = (int)src;
    g_eea[pos]  = __ldg(edge_attr + e);
}

// ============================ aggregate (per layer) =========================
// One warp per node: aggr[i] = (1+eps)*h[i] + sum_{e in-edges} relu(h[src]+ea*ew+eb)
// Pure gather — no atomics, single write per element.
__global__ void aggregate_kernel(const float* __restrict__ edge_w,
                                 const float* __restrict__ edge_b,
                                 const float* __restrict__ eps_l, int n) {
    int gt = blockIdx.x * blockDim.x + threadIdx.x;
    int i = gt >> 5;
    if (i >= n) return;
    int lane = gt & 31;
    int c = lane * 4;
    float4 ew = *(const float4*)(edge_w + c);
    float4 eb = *(const float4*)(edge_b + c);
    float s = 1.0f + __ldg(eps_l);

    float4 hv = *(const float4*)(g_h + (size_t)i * HH + c);
    float4 acc;
    acc.x = hv.x * s; acc.y = hv.y * s; acc.z = hv.z * s; acc.w = hv.w * s;

    int k0 = __ldg(&g_rowptr[i]);
    int k1 = __ldg(&g_rowptr[i + 1]);
    for (int k = k0; k < k1; k++) {
        int src = __ldg(&g_esrc[k]);     // converged -> broadcast
        float ea = __ldg(&g_eea[k]);
        float4 sv = *(const float4*)(g_h + (size_t)src * HH + c);
        acc.x += fmaxf(sv.x + fmaf(ea, ew.x, eb.x), 0.0f);
        acc.y += fmaxf(sv.y + fmaf(ea, ew.y, eb.y), 0.0f);
        acc.z += fmaxf(sv.z + fmaf(ea, ew.z, eb.z), 0.0f);
        acc.w += fmaxf(sv.w + fmaf(ea, ew.w, eb.w), 0.0f);
    }
    *(float4*)(g_aggr + (size_t)i * HH + c) = acc;
}

// ---------------------------------------------------------------------------
// C[M,128] = act(A[M,128] @ W[128,128] + bias), optional BN epilogue.
// FFMA2 inner loop; 256 threads, 128x128 tile, 8x8/thread, BK=32.
#define SA_STRIDE 130
template <int MODE, int SRC, int DST>
__global__ void __launch_bounds__(256, 2)
gemm128_kernel(const float* __restrict__ W,
               const float* __restrict__ bias,
               const float* __restrict__ bn_g,
               const float* __restrict__ bn_b,
               const float* __restrict__ bn_m,
               const float* __restrict__ bn_v,
               int M) {
    const float* A = buf_ptr(SRC);
    float*       C = buf_ptr(DST);

    __shared__ float sW[32 * HH];
    __shared__ float sA[32 * SA_STRIDE];
    int tid = threadIdx.x;
    int tx = tid & 15;               // cols tx*8..+7
    int ty = tid >> 4;               // rows ty*8..+7
    int row0 = blockIdx.x * 128;

    u64 acc[4][8];
    #pragma unroll
    for (int i = 0; i < 4; i++)
        #pragma unroll
        for (int j = 0; j < 8; j++) acc[i][j] = 0ull;

    for (int k0 = 0; k0 < HH; k0 += 32) {
        __syncthreads();
        {
            const float4* W4 = (const float4*)(W + (size_t)k0 * HH);
            float4* sW4 = (float4*)sW;
            #pragma unroll
            for (int i = 0; i < 4; i++) sW4[tid + i * 256] = W4[tid + i * 256];
        }
        #pragma unroll
        for (int s = 0; s < 16; s++) {
            int idx = tid + s * 256;
            int kk = idx & 31;
            int r  = idx >> 5;
            int grow = row0 + r;
            sA[kk * SA_STRIDE + r] =
                (grow < M) ? A[(size_t)grow * HH + k0 + kk] : 0.0f;
        }
        __syncthreads();
        #pragma unroll
        for (int kk = 0; kk < 32; kk++) {
            const u64* ap = (const u64*)(sA + kk * SA_STRIDE + ty * 8);
            u64 a2[4];
            #pragma unroll
            for (int i = 0; i < 4; i++) a2[i] = ap[i];
            float4 w0 = *(const float4*)(sW + kk * HH + tx * 8);
            float4 w1 = *(const float4*)(sW + kk * HH + tx * 8 + 4);
            u64 wd[8];
            wd[0] = dup2(w0.x); wd[1] = dup2(w0.y);
            wd[2] = dup2(w0.z); wd[3] = dup2(w0.w);
            wd[4] = dup2(w1.x); wd[5] = dup2(w1.y);
            wd[6] = dup2(w1.z); wd[7] = dup2(w1.w);
            #pragma unroll
            for (int i = 0; i < 4; i++)
                #pragma unroll
                for (int j = 0; j < 8; j++) fma2(acc[i][j], a2[i], wd[j]);
        }
    }

    float sb[8], ss[8], stt[8];
    #pragma unroll
    for (int j = 0; j < 8; j++) {
        int c = tx * 8 + j;
        sb[j] = __ldg(bias + c);
        if (MODE == 1) {
            float inv = rsqrtf(fabsf(__ldg(bn_v + c)) + 1e-5f);
            ss[j]  = __ldg(bn_g + c) * inv;
            stt[j] = __ldg(bn_b + c) - __ldg(bn_m + c) * ss[j];
        }
    }

    #pragma unroll
    for (int i = 0; i < 8; i++) {
        int r = row0 + ty * 8 + i;
        if (r < M) {
            float v[8];
            #pragma unroll
            for (int j = 0; j < 8; j++) {
                float2 p = unpack2(acc[i >> 1][j]);
                float z = ((i & 1) ? p.y : p.x) + sb[j];
                if (MODE == 1) z = fmaf(z, ss[j], stt[j]);
                v[j] = fmaxf(z, 0.0f);
            }
            float4* cp = (float4*)(C + (size_t)r * HH + tx * 8);
            cp[0] = make_float4(v[0], v[1], v[2], v[3]);
            cp[1] = make_float4(v[4], v[5], v[6], v[7]);
        }
    }
}

// ---------------------------------------------------------------------------
__global__ void zero_pool_kernel() {
    int i = blockIdx.x * blockDim.x + threadIdx.x;
    if (i < GG * HH) g_pool[i] = 0.0f;
    if (i < GG) g_cnt[i] = 0.0f;
}

__global__ void pool_kernel(const void* __restrict__ batch_raw, int n) {
    int gt = blockIdx.x * blockDim.x + threadIdx.x;
    int i = gt >> 5;
    if (i >= n) return;
    int lane = gt & 31;
    long long b;
    if (g_idx64) b = __ldg((const long long*)batch_raw + i);
    else         b = __ldg((const int*)batch_raw + i);
    if ((unsigned long long)b >= (unsigned long long)GG) return;
    int c = lane * 4;
    float4 v = *(const float4*)(g_h + (size_t)i * HH + c);
    red_add_v4(g_pool + (size_t)b * HH + c, v);
    if (lane == 0) atomicAdd(&g_cnt[b], 1.0f);
}

// ---------------------------------------------------------------------------
__global__ void classifier1_kernel(const float* __restrict__ cls_w1,
                                   const float* __restrict__ cls_b1) {
    __shared__ float sg[GG * HH];
    int tid = threadIdx.x;          // 256
    for (int i = tid; i < GG * HH; i += 256) {
        float cnt = g_cnt[i >> 7];
        sg[i] = g_pool[i] / fmaxf(cnt, 1.0f);
    }
    __syncthreads();
    for (int e = tid; e < GG * 64; e += 256) {
        int gi = e >> 6;
        int m  = e & 63;
        float s = cls_b1[m];
        #pragma unroll 8
        for (int k = 0; k < HH; k++)
            s = fmaf(sg[gi * HH + k], cls_w1[k * 64 + m], s);
        g_st[e] = fmaxf(s, 0.0f);
    }
}

__global__ void classifier2_kernel(const float* __restrict__ cls_w2,
                                   const float* __restrict__ cls_b2,
                                   float* __restrict__ out) {
    int g = threadIdx.x;
    if (g < GG) {
        float s = cls_b2[0];
        #pragma unroll 8
        for (int m = 0; m < 64; m++)
            s = fmaf(g_st[g * 64 + m], cls_w2[m], s);
        out[g] = 1.0f / (1.0f + expf(-s));
    }
}

// ---------------------------------------------------------------------------
extern "C" void kernel_launch(void* const* d_in, const int* in_sizes, int n_in,
                              void* d_out, int out_size) {
    const float *x, *edge_attr, *enc_w, *enc_b, *edge_w, *edge_b, *eps;
    const float *mlp_w1, *mlp_b1, *mlp_w2, *mlp_b2;
    const float *bn_gamma, *bn_beta, *bn_mean, *bn_var;
    const float *cls_w1, *cls_b1, *cls_w2, *cls_b2;
    const void *edge_index, *batch;
    int n, E;

    if (in_sizes[1] > 1000) {
        x          = (const float*)d_in[0];
        edge_index = d_in[1];
        edge_attr  = (const float*)d_in[2];
        batch      = d_in[3];
        enc_w      = (const float*)d_in[4];
        enc_b      = (const float*)d_in[5];
        edge_w     = (const float*)d_in[6];
        edge_b     = (const float*)d_in[7];
        eps        = (const float*)d_in[8];
        mlp_w1     = (const float*)d_in[9];
        mlp_b1     = (const float*)d_in[10];
        mlp_w2     = (const float*)d_in[11];
        mlp_b2     = (const float*)d_in[12];
        bn_gamma   = (const float*)d_in[13];
        bn_beta    = (const float*)d_in[14];
        bn_mean    = (const float*)d_in[15];
        bn_var     = (const float*)d_in[16];
        cls_w1     = (const float*)d_in[17];
        cls_b1     = (const float*)d_in[18];
        cls_w2     = (const float*)d_in[19];
        cls_b2     = (const float*)d_in[20];
        n = in_sizes[0];
        E = in_sizes[2];
    } else {
        batch      = d_in[0];
        bn_beta    = (const float*)d_in[1];
        bn_gamma   = (const float*)d_in[2];
        bn_mean    = (const float*)d_in[3];
        bn_var     = (const float*)d_in[4];
        cls_b1     = (const float*)d_in[5];
        cls_b2     = (const float*)d_in[6];
        cls_w1     = (const float*)d_in[7];
        cls_w2     = (const float*)d_in[8];
        edge_attr  = (const float*)d_in[9];
        edge_b     = (const float*)d_in[10];
        edge_index = d_in[11];
        edge_w     = (const float*)d_in[12];
        enc_b      = (const float*)d_in[13];
        enc_w      = (const float*)d_in[14];
        eps        = (const float*)d_in[15];
        mlp_b1     = (const float*)d_in[16];
        mlp_b2     = (const float*)d_in[17];
        mlp_w1     = (const float*)d_in[18];
        mlp_w2     = (const float*)d_in[19];
        x          = (const float*)d_in[20];
        n = in_sizes[20];
        E = in_sizes[9];
    }
    float* out = (float*)d_out;
    if (E > EE_MAX) E = EE_MAX;

    // 0) dtype detect
    detect_kernel<<<1, 32>>>(edge_index, n);

    // 1) encode
    encode_kernel<<<(n * 32 + 255) / 256, 256>>>(x, enc_w, enc_b, n);

    // 2) CSR build (once; graph shared by both layers)
    int nblk = (n + 255) / 256;
    zero_deg_kernel<<<nblk, 256>>>(n);
    csr_count_kernel<<<(E + 255) / 256, 256>>>(edge_index, E, n);
    blocksum_kernel<<<nblk, 256>>>(n);
    scan_bsum_kernel<<<1, 512>>>(nblk);
    rowptr_kernel<<<nblk, 256>>>(n, E);
    csr_fill_kernel<<<(E + 255) / 256, 256>>>(edge_index, edge_attr, E, n);

    // 3) layers
    int gemm_blocks = (n + 127) / 128;
    int agg_blocks = (n * 32 + 255) / 256;
    for (int l = 0; l < LL; l++) {
        aggregate_kernel<<<agg_blocks, 256>>>(edge_w, edge_b, eps + l, n);
        if (l == 0) {
            gemm128_kernel<0, BUF_AGGR, BUF_TMP><<<gemm_blocks, 256>>>(
                mlp_w1, mlp_b1, nullptr, nullptr, nullptr, nullptr, n);
            gemm128_kernel<1, BUF_TMP, BUF_H><<<gemm_blocks, 256>>>(
                mlp_w2, mlp_b2, bn_gamma, bn_beta, bn_mean, bn_var, n);
        } else {
            gemm128_kernel<0, BUF_AGGR, BUF_TMP><<<gemm_blocks, 256>>>(
                mlp_w1 + (size_t)HH * HH, mlp_b1 + HH,
                nullptr, nullptr, nullptr, nullptr, n);
            gemm128_kernel<1, BUF_TMP, BUF_H><<<gemm_blocks, 256>>>(
                mlp_w2 + (size_t)HH * HH, mlp_b2 + HH,
                bn_gamma + HH, bn_beta + HH, bn_mean + HH, bn_var + HH, n);
        }
    }

    // 4) global mean pool + classifier
    zero_pool_kernel<<<(GG * HH + 255) / 256, 256>>>();
    pool_kernel<<<(n * 32 + 255) / 256, 256>>>(batch, n);
    classifier1_kernel<<<1, 256>>>(cls_w1, cls_b1);
    classifier2_kernel<<<1, 64>>>(cls_w2, cls_b2, out);
}

// round 7
// speedup vs baseline: 2.5530x; 1.0016x over previous
#include <cuda_runtime.h>
#include <math.h>

// Fixed problem shape
#define HH 128
#define GG 64
#define NN_MAX 100000
#define EE_MAX 1600000

typedef unsigned long long u64;

// Scratch: __device__ globals, referenced ONLY inside device code.
__device__ float g_h[NN_MAX * HH];
__device__ float g_aggr[NN_MAX * HH];
__device__ float g_tmp[NN_MAX * HH];
__device__ float g_pool[GG * HH];
__device__ float g_cnt[GG];
__device__ float g_st[GG * 64];
__device__ int   g_idx64;           // 1 if edge_index/batch are int64

// CSR scratch (built once per call; graph shared by both layers)
__device__ int   g_deg[NN_MAX];
__device__ int   g_rowptr[NN_MAX + 1];
__device__ int   g_cursor[NN_MAX];
__device__ int   g_bsum[512];
__device__ int   g_boff[512];
__device__ int   g_esrc[EE_MAX];    // src node per edge, sorted by dst
__device__ float g_eea[EE_MAX];     // edge_attr per edge, sorted by dst

// Buffer selectors for the GEMM template
#define BUF_AGGR 0
#define BUF_TMP  1
#define BUF_H    2
__device__ __forceinline__ float* buf_ptr(int sel) {
    return sel == BUF_AGGR ? g_aggr : (sel == BUF_TMP ? g_tmp : g_h);
}

__device__ __forceinline__ void red_add_v4(float* p, float4 v) {
    asm volatile("red.global.add.v4.f32 [%0], {%1,%2,%3,%4};"
                 :: "l"(p), "f"(v.x), "f"(v.y), "f"(v.z), "f"(v.w)
                 : "memory");
}

// ---- packed f32x2 helpers (FFMA2) -----------------------------------------
__device__ __forceinline__ u64 dup2(float v) {
    u64 r; asm("mov.b64 %0, {%1,%2};" : "=l"(r) : "f"(v), "f"(v)); return r;
}
__device__ __forceinline__ void fma2(u64& d, u64 a, u64 b) {
    asm("fma.rn.f32x2 %0, %1, %2, %0;" : "+l"(d) : "l"(a), "l"(b));
}
__device__ __forceinline__ float2 unpack2(u64 v) {
    float2 r; asm("mov.b64 {%0,%1}, %2;" : "=f"(r.x), "=f"(r.y) : "l"(v));
    return r;
}

// ---------------------------------------------------------------------------
__global__ void detect_kernel(const void* ei_raw, int n) {
    if (threadIdx.x == 0 && blockIdx.x == 0) {
        const long long* p = (const long long*)ei_raw;
        int ok = 1;
        for (int i = 0; i < 16; i++) {
            long long v = p[i];
            if (v < 0 || v >= (long long)n) ok = 0;
        }
        g_idx64 = ok;
    }
}

// ============================ CSR build (once) =============================
__global__ void zero_deg_kernel(int n) {
    int i = blockIdx.x * blockDim.x + threadIdx.x;
    if (i < n) g_deg[i] = 0;
}

__global__ void csr_count_kernel(const void* __restrict__ ei_raw, int E, int n) {
    int e = blockIdx.x * blockDim.x + threadIdx.x;
    if (e >= E) return;
    long long dst;
    if (g_idx64) dst = __ldg((const long long*)ei_raw + E + e);
    else         dst = __ldg((const int*)ei_raw + E + e);
    if ((unsigned long long)dst >= (unsigned long long)n) return;
    atomicAdd(&g_deg[(int)dst], 1);
}

__global__ void blocksum_kernel(int n) {
    __shared__ int s[256];
    int t = threadIdx.x;
    int i = blockIdx.x * 256 + t;
    s[t] = (i < n) ? g_deg[i] : 0;
    __syncthreads();
    for (int d = 128; d > 0; d >>= 1) {
        if (t < d) s[t] += s[t + d];
        __syncthreads();
    }
    if (t == 0) g_bsum[blockIdx.x] = s[0];
}

__global__ void scan_bsum_kernel(int nb) {
    __shared__ int s[512];
    int t = threadIdx.x;
    int v0 = (t < nb) ? g_bsum[t] : 0;
    s[t] = v0;
    __syncthreads();
    for (int d = 1; d < 512; d <<= 1) {
        int v = (t >= d) ? s[t - d] : 0;
        __syncthreads();
        s[t] += v;
        __syncthreads();
    }
    g_boff[t] = s[t] - v0;   // exclusive
}

__global__ void rowptr_kernel(int n, int E) {
    __shared__ int s[256];
    int t = threadIdx.x;
    int i = blockIdx.x * 256 + t;
    int d = (i < n) ? g_deg[i] : 0;
    s[t] = d;
    __syncthreads();
    for (int dd = 1; dd < 256; dd <<= 1) {
        int v = (t >= dd) ? s[t - dd] : 0;
        __syncthreads();
        s[t] += v;
        __syncthreads();
    }
    int excl = s[t] - d + g_boff[blockIdx.x];
    if (i < n) {
        g_rowptr[i] = excl;
        g_cursor[i] = excl;
        if (i == n - 1) g_rowptr[n] = E;
    }
}

__global__ void csr_fill_kernel(const void* __restrict__ ei_raw,
                                const float* __restrict__ edge_attr,
                                int E, int n) {
    int e = blockIdx.x * blockDim.x + threadIdx.x;
    if (e >= E) return;
    long long src, dst;
    if (g_idx64) {
        const long long* ei = (const long long*)ei_raw;
        src = __ldg(ei + e);
        dst = __ldg(ei + E + e);
    } else {
        const int* ei = (const int*)ei_raw;
        src = __ldg(ei + e);
        dst = __ldg(ei + E + e);
    }
    if ((unsigned long long)src >= (unsigned long long)n ||
        (unsigned long long)dst >= (unsigned long long)n) return;
    int pos = atomicAdd(&g_cursor[(int)dst], 1);
    g_esrc[pos] = (int)src;
    g_eea[pos]  = __ldg(edge_attr + e);
}

// ==================== aggregate layer 0 (rank-1 h) ==========================
// h[j] = x[j]*enc_w + enc_b is rank-1: recompute h[src] from the SCALAR x[src]
// instead of gathering 512B rows. aggr[i] = (1+eps0)*h_i + sum relu(h_src + e).
__global__ void aggregate_l0_kernel(const float* __restrict__ x,
                                    const float* __restrict__ enc_w,
                                    const float* __restrict__ enc_b,
                                    const float* __restrict__ edge_w,
                                    const float* __restrict__ edge_b,
                                    const float* __restrict__ eps0, int n) {
    int gt = blockIdx.x * blockDim.x + threadIdx.x;
    int i = gt >> 5;
    if (i >= n) return;
    int lane = gt & 31;
    int c = lane * 4;
    float4 cw = *(const float4*)(enc_w + c);
    float4 cb = *(const float4*)(enc_b + c);
    float4 ew = *(const float4*)(edge_w + c);
    float4 eb = *(const float4*)(edge_b + c);
    // fold edge bias into encoder bias for the message term: m = relu(x_s*cw + (cb+eb) + ea*ew)
    float4 mb;
    mb.x = cb.x + eb.x; mb.y = cb.y + eb.y;
    mb.z = cb.z + eb.z; mb.w = cb.w + eb.w;
    float s = 1.0f + __ldg(eps0);
    float xi = __ldg(x + i);
    float4 acc;
    acc.x = s * fmaf(xi, cw.x, cb.x);
    acc.y = s * fmaf(xi, cw.y, cb.y);
    acc.z = s * fmaf(xi, cw.z, cb.z);
    acc.w = s * fmaf(xi, cw.w, cb.w);

    int k0 = __ldg(&g_rowptr[i]);
    int k1 = __ldg(&g_rowptr[i + 1]);
    for (int k = k0; k < k1; k++) {
        float xs = __ldg(x + __ldg(&g_esrc[k]));
        float ea = __ldg(&g_eea[k]);
        acc.x += fmaxf(fmaf(xs, cw.x, fmaf(ea, ew.x, mb.x)), 0.0f);
        acc.y += fmaxf(fmaf(xs, cw.y, fmaf(ea, ew.y, mb.y)), 0.0f);
        acc.z += fmaxf(fmaf(xs, cw.z, fmaf(ea, ew.z, mb.z)), 0.0f);
        acc.w += fmaxf(fmaf(xs, cw.w, fmaf(ea, ew.w, mb.w)), 0.0f);
    }
    *(float4*)(g_aggr + (size_t)i * HH + c) = acc;
}

// ==================== aggregate layer 1 (dense h gather) ====================
// One warp per node, unroll-4 edge prefetch for memory-level parallelism.
__global__ void aggregate_kernel(const float* __restrict__ edge_w,
                                 const float* __restrict__ edge_b,
                                 const float* __restrict__ eps_l, int n) {
    int gt = blockIdx.x * blockDim.x + threadIdx.x;
    int i = gt >> 5;
    if (i >= n) return;
    int lane = gt & 31;
    int c = lane * 4;
    float4 ew = *(const float4*)(edge_w + c);
    float4 eb = *(const float4*)(edge_b + c);
    float s = 1.0f + __ldg(eps_l);

    float4 hv = *(const float4*)(g_h + (size_t)i * HH + c);
    float4 acc;
    acc.x = hv.x * s; acc.y = hv.y * s; acc.z = hv.z * s; acc.w = hv.w * s;

    int k0 = __ldg(&g_rowptr[i]);
    int k1 = __ldg(&g_rowptr[i + 1]);
    int k = k0;
    for (; k + 4 <= k1; k += 4) {
        int s0 = __ldg(&g_esrc[k]);
        int s1 = __ldg(&g_esrc[k + 1]);
        int s2 = __ldg(&g_esrc[k + 2]);
        int s3 = __ldg(&g_esrc[k + 3]);
        float a0 = __ldg(&g_eea[k]);
        float a1 = __ldg(&g_eea[k + 1]);
        float a2 = __ldg(&g_eea[k + 2]);
        float a3 = __ldg(&g_eea[k + 3]);
        float4 v0 = *(const float4*)(g_h + (size_t)s0 * HH + c);
        float4 v1 = *(const float4*)(g_h + (size_t)s1 * HH + c);
        float4 v2 = *(const float4*)(g_h + (size_t)s2 * HH + c);
        float4 v3 = *(const float4*)(g_h + (size_t)s3 * HH + c);
        acc.x += fmaxf(v0.x + fmaf(a0, ew.x, eb.x), 0.0f);
        acc.y += fmaxf(v0.y + fmaf(a0, ew.y, eb.y), 0.0f);
        acc.z += fmaxf(v0.z + fmaf(a0, ew.z, eb.z), 0.0f);
        acc.w += fmaxf(v0.w + fmaf(a0, ew.w, eb.w), 0.0f);
        acc.x += fmaxf(v1.x + fmaf(a1, ew.x, eb.x), 0.0f);
        acc.y += fmaxf(v1.y + fmaf(a1, ew.y, eb.y), 0.0f);
        acc.z += fmaxf(v1.z + fmaf(a1, ew.z, eb.z), 0.0f);
        acc.w += fmaxf(v1.w + fmaf(a1, ew.w, eb.w), 0.0f);
        acc.x += fmaxf(v2.x + fmaf(a2, ew.x, eb.x), 0.0f);
        acc.y += fmaxf(v2.y + fmaf(a2, ew.y, eb.y), 0.0f);
        acc.z += fmaxf(v2.z + fmaf(a2, ew.z, eb.z), 0.0f);
        acc.w += fmaxf(v2.w + fmaf(a2, ew.w, eb.w), 0.0f);
        acc.x += fmaxf(v3.x + fmaf(a3, ew.x, eb.x), 0.0f);
        acc.y += fmaxf(v3.y + fmaf(a3, ew.y, eb.y), 0.0f);
        acc.z += fmaxf(v3.z + fmaf(a3, ew.z, eb.z), 0.0f);
        acc.w += fmaxf(v3.w + fmaf(a3, ew.w, eb.w), 0.0f);
    }
    for (; k < k1; k++) {
        int src = __ldg(&g_esrc[k]);
        float ea = __ldg(&g_eea[k]);
        float4 sv = *(const float4*)(g_h + (size_t)src * HH + c);
        acc.x += fmaxf(sv.x + fmaf(ea, ew.x, eb.x), 0.0f);
        acc.y += fmaxf(sv.y + fmaf(ea, ew.y, eb.y), 0.0f);
        acc.z += fmaxf(sv.z + fmaf(ea, ew.z, eb.z), 0.0f);
        acc.w += fmaxf(sv.w + fmaf(ea, ew.w, eb.w), 0.0f);
    }
    *(float4*)(g_aggr + (size_t)i * HH + c) = acc;
}

// ---------------------------------------------------------------------------
// C[M,128] = act(A[M,128] @ W[128,128] + bias), optional BN epilogue.
// FFMA2 inner loop; 256 threads, 128x128 tile, 8x8/thread, BK=32.
// POOL=1 (implies MODE 1): instead of storing C, red.v4 result rows into
// g_pool[batch[r]] (global mean pool numerator), since h is dead afterwards.
#define SA_STRIDE 130
template <int MODE, int SRC, int DST, int POOL>
__global__ void __launch_bounds__(256, 2)
gemm128_kernel(const float* __restrict__ W,
               const float* __restrict__ bias,
               const float* __restrict__ bn_g,
               const float* __restrict__ bn_b,
               const float* __restrict__ bn_m,
               const float* __restrict__ bn_v,
               const void* __restrict__ batch_raw,
               int M) {
    const float* A = buf_ptr(SRC);
    float*       C = buf_ptr(DST);

    __shared__ float sW[32 * HH];
    __shared__ float sA[32 * SA_STRIDE];
    int tid = threadIdx.x;
    int tx = tid & 15;               // cols tx*8..+7
    int ty = tid >> 4;               // rows ty*8..+7
    int row0 = blockIdx.x * 128;

    u64 acc[4][8];
    #pragma unroll
    for (int i = 0; i < 4; i++)
        #pragma unroll
        for (int j = 0; j < 8; j++) acc[i][j] = 0ull;

    for (int k0 = 0; k0 < HH; k0 += 32) {
        __syncthreads();
        {
            const float4* W4 = (const float4*)(W + (size_t)k0 * HH);
            float4* sW4 = (float4*)sW;
            #pragma unroll
            for (int i = 0; i < 4; i++) sW4[tid + i * 256] = W4[tid + i * 256];
        }
        #pragma unroll
        for (int s = 0; s < 16; s++) {
            int idx = tid + s * 256;
            int kk = idx & 31;
            int r  = idx >> 5;
            int grow = row0 + r;
            sA[kk * SA_STRIDE + r] =
                (grow < M) ? A[(size_t)grow * HH + k0 + kk] : 0.0f;
        }
        __syncthreads();
        #pragma unroll
        for (int kk = 0; kk < 32; kk++) {
            const u64* ap = (const u64*)(sA + kk * SA_STRIDE + ty * 8);
            u64 a2[4];
            #pragma unroll
            for (int i = 0; i < 4; i++) a2[i] = ap[i];
            float4 w0 = *(const float4*)(sW + kk * HH + tx * 8);
            float4 w1 = *(const float4*)(sW + kk * HH + tx * 8 + 4);
            u64 wd[8];
            wd[0] = dup2(w0.x); wd[1] = dup2(w0.y);
            wd[2] = dup2(w0.z); wd[3] = dup2(w0.w);
            wd[4] = dup2(w1.x); wd[5] = dup2(w1.y);
            wd[6] = dup2(w1.z); wd[7] = dup2(w1.w);
            #pragma unroll
            for (int i = 0; i < 4; i++)
                #pragma unroll
                for (int j = 0; j < 8; j++) fma2(acc[i][j], a2[i], wd[j]);
        }
    }

    float sb[8], ss[8], stt[8];
    #pragma unroll
    for (int j = 0; j < 8; j++) {
        int c = tx * 8 + j;
        sb[j] = __ldg(bias + c);
        if (MODE == 1) {
            float inv = rsqrtf(fabsf(__ldg(bn_v + c)) + 1e-5f);
            ss[j]  = __ldg(bn_g + c) * inv;
            stt[j] = __ldg(bn_b + c) - __ldg(bn_m + c) * ss[j];
        }
    }

    #pragma unroll
    for (int i = 0; i < 8; i++) {
        int r = row0 + ty * 8 + i;
        if (r < M) {
            float v[8];
            #pragma unroll
            for (int j = 0; j < 8; j++) {
                float2 p = unpack2(acc[i >> 1][j]);
                float z = ((i & 1) ? p.y : p.x) + sb[j];
                if (MODE == 1) z = fmaf(z, ss[j], stt[j]);
                v[j] = fmaxf(z, 0.0f);
            }
            if (POOL) {
                long long b;
                if (g_idx64) b = __ldg((const long long*)batch_raw + r);
                else         b = __ldg((const int*)batch_raw + r);
                if ((unsigned long long)b < (unsigned long long)GG) {
                    float* pp = g_pool + (size_t)b * HH + tx * 8;
                    red_add_v4(pp,     make_float4(v[0], v[1], v[2], v[3]));
                    red_add_v4(pp + 4, make_float4(v[4], v[5], v[6], v[7]));
                }
            } else {
                float4* cp = (float4*)(C + (size_t)r * HH + tx * 8);
                cp[0] = make_float4(v[0], v[1], v[2], v[3]);
                cp[1] = make_float4(v[4], v[5], v[6], v[7]);
            }
        }
    }
}

// ---------------------------------------------------------------------------
__global__ void zero_pool_kernel() {
    int i = blockIdx.x * blockDim.x + threadIdx.x;
    if (i < GG * HH) g_pool[i] = 0.0f;
    if (i < GG) g_cnt[i] = 0.0f;
}

// per-graph node counts (batch sorted -> ptxas REDUX-aggregates the atomics)
__global__ void cnt_kernel(const void* __restrict__ batch_raw, int n) {
    int i = blockIdx.x * blockDim.x + threadIdx.x;
    if (i >= n) return;
    long long b;
    if (g_idx64) b = __ldg((const long long*)batch_raw + i);
    else         b = __ldg((const int*)batch_raw + i);
    if ((unsigned long long)b < (unsigned long long)GG)
        atomicAdd(&g_cnt[b], 1.0f);
}

// ---------------------------------------------------------------------------
__global__ void classifier1_kernel(const float* __restrict__ cls_w1,
                                   const float* __restrict__ cls_b1) {
    __shared__ float sg[GG * HH];
    int tid = threadIdx.x;          // 256
    for (int i = tid; i < GG * HH; i += 256) {
        float cnt = g_cnt[i >> 7];
        sg[i] = g_pool[i] / fmaxf(cnt, 1.0f);
    }
    __syncthreads();
    for (int e = tid; e < GG * 64; e += 256) {
        int gi = e >> 6;
        int m  = e & 63;
        float s = cls_b1[m];
        #pragma unroll 8
        for (int k = 0; k < HH; k++)
            s = fmaf(sg[gi * HH + k], cls_w1[k * 64 + m], s);
        g_st[e] = fmaxf(s, 0.0f);
    }
}

__global__ void classifier2_kernel(const float* __restrict__ cls_w2,
                                   const float* __restrict__ cls_b2,
                                   float* __restrict__ out) {
    int g = threadIdx.x;
    if (g < GG) {
        float s = cls_b2[0];
        #pragma unroll 8
        for (int m = 0; m < 64; m++)
            s = fmaf(g_st[g * 64 + m], cls_w2[m], s);
        out[g] = 1.0f / (1.0f + expf(-s));
    }
}

// ---------------------------------------------------------------------------
extern "C" void kernel_launch(void* const* d_in, const int* in_sizes, int n_in,
                              void* d_out, int out_size) {
    const float *x, *edge_attr, *enc_w, *enc_b, *edge_w, *edge_b, *eps;
    const float *mlp_w1, *mlp_b1, *mlp_w2, *mlp_b2;
    const float *bn_gamma, *bn_beta, *bn_mean, *bn_var;
    const float *cls_w1, *cls_b1, *cls_w2, *cls_b2;
    const void *edge_index, *batch;
    int n, E;

    if (in_sizes[1] > 1000) {
        x          = (const float*)d_in[0];
        edge_index = d_in[1];
        edge_attr  = (const float*)d_in[2];
        batch      = d_in[3];
        enc_w      = (const float*)d_in[4];
        enc_b      = (const float*)d_in[5];
        edge_w     = (const float*)d_in[6];
        edge_b     = (const float*)d_in[7];
        eps        = (const float*)d_in[8];
        mlp_w1     = (const float*)d_in[9];
        mlp_b1     = (const float*)d_in[10];
        mlp_w2     = (const float*)d_in[11];
        mlp_b2     = (const float*)d_in[12];
        bn_gamma   = (const float*)d_in[13];
        bn_beta    = (const float*)d_in[14];
        bn_mean    = (const float*)d_in[15];
        bn_var     = (const float*)d_in[16];
        cls_w1     = (const float*)d_in[17];
        cls_b1     = (const float*)d_in[18];
        cls_w2     = (const float*)d_in[19];
        cls_b2     = (const float*)d_in[20];
        n = in_sizes[0];
        E = in_sizes[2];
    } else {
        batch      = d_in[0];
        bn_beta    = (const float*)d_in[1];
        bn_gamma   = (const float*)d_in[2];
        bn_mean    = (const float*)d_in[3];
        bn_var     = (const float*)d_in[4];
        cls_b1     = (const float*)d_in[5];
        cls_b2     = (const float*)d_in[6];
        cls_w1     = (const float*)d_in[7];
        cls_w2     = (const float*)d_in[8];
        edge_attr  = (const float*)d_in[9];
        edge_b     = (const float*)d_in[10];
        edge_index = d_in[11];
        edge_w     = (const float*)d_in[12];
        enc_b      = (const float*)d_in[13];
        enc_w      = (const float*)d_in[14];
        eps        = (const float*)d_in[15];
        mlp_b1     = (const float*)d_in[16];
        mlp_b2     = (const float*)d_in[17];
        mlp_w1     = (const float*)d_in[18];
        mlp_w2     = (const float*)d_in[19];
        x          = (const float*)d_in[20];
        n = in_sizes[20];
        E = in_sizes[9];
    }
    float* out = (float*)d_out;
    if (E > EE_MAX) E = EE_MAX;

    // 0) dtype detect + pool zero + per-graph counts
    detect_kernel<<<1, 32>>>(edge_index, n);
    zero_pool_kernel<<<(GG * HH + 255) / 256, 256>>>();
    cnt_kernel<<<(n + 255) / 256, 256>>>(batch, n);

    // 1) CSR build (once; graph shared by both layers)
    int nblk = (n + 255) / 256;
    zero_deg_kernel<<<nblk, 256>>>(n);
    csr_count_kernel<<<(E + 255) / 256, 256>>>(edge_index, E, n);
    blocksum_kernel<<<nblk, 256>>>(n);
    scan_bsum_kernel<<<1, 512>>>(nblk);
    rowptr_kernel<<<nblk, 256>>>(n, E);
    csr_fill_kernel<<<(E + 255) / 256, 256>>>(edge_index, edge_attr, E, n);

    // 2) layers
    int gemm_blocks = (n + 127) / 128;
    int agg_blocks = (n * 32 + 255) / 256;

    // layer 0: rank-1 aggregate (no encode kernel needed)
    aggregate_l0_kernel<<<agg_blocks, 256>>>(x, enc_w, enc_b, edge_w, edge_b,
                                             eps, n);
    gemm128_kernel<0, BUF_AGGR, BUF_TMP, 0><<<gemm_blocks, 256>>>(
        mlp_w1, mlp_b1, nullptr, nullptr, nullptr, nullptr, nullptr, n);
    gemm128_kernel<1, BUF_TMP, BUF_H, 0><<<gemm_blocks, 256>>>(
        mlp_w2, mlp_b2, bn_gamma, bn_beta, bn_mean, bn_var, nullptr, n);

    // layer 1: dense aggregate + MLP; last GEMM pools directly
    aggregate_kernel<<<agg_blocks, 256>>>(edge_w, edge_b, eps + 1, n);
    gemm128_kernel<0, BUF_AGGR, BUF_TMP, 0><<<gemm_blocks, 256>>>(
        mlp_w1 + (size_t)HH * HH, mlp_b1 + HH,
        nullptr, nullptr, nullptr, nullptr, nullptr, n);
    gemm128_kernel<1, BUF_TMP, BUF_H, 1><<<gemm_blocks, 256>>>(
        mlp_w2 + (size_t)HH * HH, mlp_b2 + HH,
        bn_gamma + HH, bn_beta + HH, bn_mean + HH, bn_var + HH, batch, n);

    // 3) classifier
    classifier1_kernel<<<1, 256>>>(cls_w1, cls_b1);
    classifier2_kernel<<<1, 64>>>(cls_w2, cls_b2, out);
}

// round 8
// speedup vs baseline: 2.7288x; 1.0689x over previous
#include <cuda_runtime.h>
#include <math.h>

// Fixed problem shape
#define HH 128
#define GG 64
#define NN_MAX 100000
#define EE_MAX 1600000

typedef unsigned long long u64;
typedef unsigned int u32;

// Scratch: __device__ globals, referenced ONLY inside device code.
__device__ float g_h[NN_MAX * HH];
__device__ float g_aggr[NN_MAX * HH];
__device__ float g_tmp[NN_MAX * HH];
__device__ float g_pool[GG * HH];
__device__ float g_cnt[GG];
__device__ float g_st[GG * 64];
__device__ int   g_idx64;           // 1 if edge_index/batch are int64

// CSR scratch (built once per call; graph shared by both layers)
__device__ int   g_deg[NN_MAX];
__device__ int   g_rowptr[NN_MAX + 1];
__device__ int   g_cursor[NN_MAX];
__device__ int   g_bsum[512];
__device__ int   g_boff[512];
__device__ int   g_esrc[EE_MAX];
__device__ float g_eea[EE_MAX];

#define BUF_AGGR 0
#define BUF_TMP  1
#define BUF_H    2
__device__ __forceinline__ float* buf_ptr(int sel) {
    return sel == BUF_AGGR ? g_aggr : (sel == BUF_TMP ? g_tmp : g_h);
}

__device__ __forceinline__ void red_add_v2(float* p, float a, float b) {
    asm volatile("red.global.add.v2.f32 [%0], {%1,%2};"
                 :: "l"(p), "f"(a), "f"(b) : "memory");
}

// tf32 helpers
__device__ __forceinline__ u32 f2tf32(float x) {
    u32 r; asm("cvt.rna.tf32.f32 %0, %1;" : "=r"(r) : "f"(x)); return r;
}
__device__ __forceinline__ void mma_tf32(float d[4], const u32 a[4],
                                         const u32 b[2]) {
    asm("mma.sync.aligned.m16n8k8.row.col.f32.tf32.tf32.f32 "
        "{%0,%1,%2,%3}, {%4,%5,%6,%7}, {%8,%9}, {%0,%1,%2,%3};"
        : "+f"(d[0]), "+f"(d[1]), "+f"(d[2]), "+f"(d[3])
        : "r"(a[0]), "r"(a[1]), "r"(a[2]), "r"(a[3]), "r"(b[0]), "r"(b[1]));
}

// ---------------------------------------------------------------------------
__global__ void detect_kernel(const void* ei_raw, int n) {
    if (threadIdx.x == 0 && blockIdx.x == 0) {
        const long long* p = (const long long*)ei_raw;
        int ok = 1;
        for (int i = 0; i < 16; i++) {
            long long v = p[i];
            if (v < 0 || v >= (long long)n) ok = 0;
        }
        g_idx64 = ok;
    }
}

// ============================ CSR build (once) =============================
__global__ void zero_deg_kernel(int n) {
    int i = blockIdx.x * blockDim.x + threadIdx.x;
    if (i < n) g_deg[i] = 0;
}

__global__ void csr_count_kernel(const void* __restrict__ ei_raw, int E, int n) {
    int e = blockIdx.x * blockDim.x + threadIdx.x;
    if (e >= E) return;
    long long dst;
    if (g_idx64) dst = __ldg((const long long*)ei_raw + E + e);
    else         dst = __ldg((const int*)ei_raw + E + e);
    if ((unsigned long long)dst >= (unsigned long long)n) return;
    atomicAdd(&g_deg[(int)dst], 1);
}

__global__ void blocksum_kernel(int n) {
    __shared__ int s[256];
    int t = threadIdx.x;
    int i = blockIdx.x * 256 + t;
    s[t] = (i < n) ? g_deg[i] : 0;
    __syncthreads();
    for (int d = 128; d > 0; d >>= 1) {
        if (t < d) s[t] += s[t + d];
        __syncthreads();
    }
    if (t == 0) g_bsum[blockIdx.x] = s[0];
}

__global__ void scan_bsum_kernel(int nb) {
    __shared__ int s[512];
    int t = threadIdx.x;
    int v0 = (t < nb) ? g_bsum[t] : 0;
    s[t] = v0;
    __syncthreads();
    for (int d = 1; d < 512; d <<= 1) {
        int v = (t >= d) ? s[t - d] : 0;
        __syncthreads();
        s[t] += v;
        __syncthreads();
    }
    g_boff[t] = s[t] - v0;
}

__global__ void rowptr_kernel(int n, int E) {
    __shared__ int s[256];
    int t = threadIdx.x;
    int i = blockIdx.x * 256 + t;
    int d = (i < n) ? g_deg[i] : 0;
    s[t] = d;
    __syncthreads();
    for (int dd = 1; dd < 256; dd <<= 1) {
        int v = (t >= dd) ? s[t - dd] : 0;
        __syncthreads();
        s[t] += v;
        __syncthreads();
    }
    int excl = s[t] - d + g_boff[blockIdx.x];
    if (i < n) {
        g_rowptr[i] = excl;
        g_cursor[i] = excl;
        if (i == n - 1) g_rowptr[n] = E;
    }
}

__global__ void csr_fill_kernel(const void* __restrict__ ei_raw,
                                const float* __restrict__ edge_attr,
                                int E, int n) {
    int e = blockIdx.x * blockDim.x + threadIdx.x;
    if (e >= E) return;
    long long src, dst;
    if (g_idx64) {
        const long long* ei = (const long long*)ei_raw;
        src = __ldg(ei + e);
        dst = __ldg(ei + E + e);
    } else {
        const int* ei = (const int*)ei_raw;
        src = __ldg(ei + e);
        dst = __ldg(ei + E + e);
    }
    if ((unsigned long long)src >= (unsigned long long)n ||
        (unsigned long long)dst >= (unsigned long long)n) return;
    int pos = atomicAdd(&g_cursor[(int)dst], 1);
    g_esrc[pos] = (int)src;
    g_eea[pos]  = __ldg(edge_attr + e);
}

// ==================== aggregate layer 0 (rank-1 h) ==========================
__global__ void aggregate_l0_kernel(const float* __restrict__ x,
                                    const float* __restrict__ enc_w,
                                    const float* __restrict__ enc_b,
                                    const float* __restrict__ edge_w,
                                    const float* __restrict__ edge_b,
                                    const float* __restrict__ eps0, int n) {
    int gt = blockIdx.x * blockDim.x + threadIdx.x;
    int i = gt >> 5;
    if (i >= n) return;
    int lane = gt & 31;
    int c = lane * 4;
    float4 cw = *(const float4*)(enc_w + c);
    float4 cb = *(const float4*)(enc_b + c);
    float4 ew = *(const float4*)(edge_w + c);
    float4 eb = *(const float4*)(edge_b + c);
    float4 mb;
    mb.x = cb.x + eb.x; mb.y = cb.y + eb.y;
    mb.z = cb.z + eb.z; mb.w = cb.w + eb.w;
    float s = 1.0f + __ldg(eps0);
    float xi = __ldg(x + i);
    float4 acc;
    acc.x = s * fmaf(xi, cw.x, cb.x);
    acc.y = s * fmaf(xi, cw.y, cb.y);
    acc.z = s * fmaf(xi, cw.z, cb.z);
    acc.w = s * fmaf(xi, cw.w, cb.w);

    int k0 = __ldg(&g_rowptr[i]);
    int k1 = __ldg(&g_rowptr[i + 1]);
    for (int k = k0; k < k1; k++) {
        float xs = __ldg(x + __ldg(&g_esrc[k]));
        float ea = __ldg(&g_eea[k]);
        acc.x += fmaxf(fmaf(xs, cw.x, fmaf(ea, ew.x, mb.x)), 0.0f);
        acc.y += fmaxf(fmaf(xs, cw.y, fmaf(ea, ew.y, mb.y)), 0.0f);
        acc.z += fmaxf(fmaf(xs, cw.z, fmaf(ea, ew.z, mb.z)), 0.0f);
        acc.w += fmaxf(fmaf(xs, cw.w, fmaf(ea, ew.w, mb.w)), 0.0f);
    }
    *(float4*)(g_aggr + (size_t)i * HH + c) = acc;
}

// ==================== aggregate layer 1 (dense h gather) ====================
__global__ void aggregate_kernel(const float* __restrict__ edge_w,
                                 const float* __restrict__ edge_b,
                                 const float* __restrict__ eps_l, int n) {
    int gt = blockIdx.x * blockDim.x + threadIdx.x;
    int i = gt >> 5;
    if (i >= n) return;
    int lane = gt & 31;
    int c = lane * 4;
    float4 ew = *(const float4*)(edge_w + c);
    float4 eb = *(const float4*)(edge_b + c);
    float s = 1.0f + __ldg(eps_l);

    float4 hv = *(const float4*)(g_h + (size_t)i * HH + c);
    float4 acc;
    acc.x = hv.x * s; acc.y = hv.y * s; acc.z = hv.z * s; acc.w = hv.w * s;

    int k0 = __ldg(&g_rowptr[i]);
    int k1 = __ldg(&g_rowptr[i + 1]);
    int k = k0;
    for (; k + 4 <= k1; k += 4) {
        int s0 = __ldg(&g_esrc[k]);
        int s1 = __ldg(&g_esrc[k + 1]);
        int s2 = __ldg(&g_esrc[k + 2]);
        int s3 = __ldg(&g_esrc[k + 3]);
        float a0 = __ldg(&g_eea[k]);
        float a1 = __ldg(&g_eea[k + 1]);
        float a2 = __ldg(&g_eea[k + 2]);
        float a3 = __ldg(&g_eea[k + 3]);
        float4 v0 = *(const float4*)(g_h + (size_t)s0 * HH + c);
        float4 v1 = *(const float4*)(g_h + (size_t)s1 * HH + c);
        float4 v2 = *(const float4*)(g_h + (size_t)s2 * HH + c);
        float4 v3 = *(const float4*)(g_h + (size_t)s3 * HH + c);
        acc.x += fmaxf(v0.x + fmaf(a0, ew.x, eb.x), 0.0f);
        acc.y += fmaxf(v0.y + fmaf(a0, ew.y, eb.y), 0.0f);
        acc.z += fmaxf(v0.z + fmaf(a0, ew.z, eb.z), 0.0f);
        acc.w += fmaxf(v0.w + fmaf(a0, ew.w, eb.w), 0.0f);
        acc.x += fmaxf(v1.x + fmaf(a1, ew.x, eb.x), 0.0f);
        acc.y += fmaxf(v1.y + fmaf(a1, ew.y, eb.y), 0.0f);
        acc.z += fmaxf(v1.z + fmaf(a1, ew.z, eb.z), 0.0f);
        acc.w += fmaxf(v1.w + fmaf(a1, ew.w, eb.w), 0.0f);
        acc.x += fmaxf(v2.x + fmaf(a2, ew.x, eb.x), 0.0f);
        acc.y += fmaxf(v2.y + fmaf(a2, ew.y, eb.y), 0.0f);
        acc.z += fmaxf(v2.z + fmaf(a2, ew.z, eb.z), 0.0f);
        acc.w += fmaxf(v2.w + fmaf(a2, ew.w, eb.w), 0.0f);
        acc.x += fmaxf(v3.x + fmaf(a3, ew.x, eb.x), 0.0f);
        acc.y += fmaxf(v3.y + fmaf(a3, ew.y, eb.y), 0.0f);
        acc.z += fmaxf(v3.z + fmaf(a3, ew.z, eb.z), 0.0f);
        acc.w += fmaxf(v3.w + fmaf(a3, ew.w, eb.w), 0.0f);
    }
    for (; k < k1; k++) {
        int src = __ldg(&g_esrc[k]);
        float ea = __ldg(&g_eea[k]);
        float4 sv = *(const float4*)(g_h + (size_t)src * HH + c);
        acc.x += fmaxf(sv.x + fmaf(ea, ew.x, eb.x), 0.0f);
        acc.y += fmaxf(sv.y + fmaf(ea, ew.y, eb.y), 0.0f);
        acc.z += fmaxf(sv.z + fmaf(ea, ew.z, eb.z), 0.0f);
        acc.w += fmaxf(sv.w + fmaf(ea, ew.w, eb.w), 0.0f);
    }
    *(float4*)(g_aggr + (size_t)i * HH + c) = acc;
}

// ---------------------------------------------------------------------------
// Tensor-core GEMM (3xTF32): C[M,128] = act(A[M,128] @ W[128,128] + bias).
// mma.m16n8k8.tf32, 8 warps (2x4), warp tile 64x32, fp32 accum, BK=16 chunks.
// A = ah + al, W = wh + wl (tf32 splits): D += ah*wh + ah*wl + al*wh.
// MODE 0: bias+relu -> DST.  MODE 1: bias+BN+relu -> DST.
// POOL=1: red.v2 result rows into g_pool[batch[r]] instead of storing C.
#define BK 16
#define SWS 136   // smem stride: 8*tig+g unique mod 32 -> conflict-free frags
template <int MODE, int SRC, int DST, int POOL>
__global__ void __launch_bounds__(256, 2)
gemm128_kernel(const float* __restrict__ W,
               const float* __restrict__ bias,
               const float* __restrict__ bn_g,
               const float* __restrict__ bn_b,
               const float* __restrict__ bn_m,
               const float* __restrict__ bn_v,
               const void* __restrict__ batch_raw,
               int M) {
    const float* A = buf_ptr(SRC);
    float*       C = buf_ptr(DST);

    __shared__ float sAh[BK * SWS], sAl[BK * SWS];
    __shared__ float sWh[BK * SWS], sWl[BK * SWS];

    int tid = threadIdx.x;
    int lane = tid & 31;
    int wid = tid >> 5;
    int g = lane >> 2;       // group id 0..7
    int tig = lane & 3;      // thread-in-group 0..3
    int wr = wid >> 2;       // warp row 0..1 (64 rows each)
    int wc = wid & 3;        // warp col 0..3 (32 cols each)
    int row0 = blockIdx.x * 128;

    float d[4][4][4];        // [mtile][ntile][reg]
    #pragma unroll
    for (int i = 0; i < 4; i++)
        #pragma unroll
        for (int j = 0; j < 4; j++)
            #pragma unroll
            for (int r = 0; r < 4; r++) d[i][j][r] = 0.0f;

    for (int k0 = 0; k0 < HH; k0 += BK) {
        __syncthreads();
        // fill W chunk [BK x 128], split into tf32 hi/lo
        #pragma unroll
        for (int s = 0; s < 8; s++) {
            int idx = tid + s * 256;
            int kk = idx >> 7;
            int c  = idx & 127;
            float w = __ldg(W + (size_t)(k0 + kk) * HH + c);
            u32 whb = f2tf32(w);
            float whf = __uint_as_float(whb);
            u32 wlb = f2tf32(w - whf);
            sWh[kk * SWS + c] = whf;
            sWl[kk * SWS + c] = __uint_as_float(wlb);
        }
        // fill A chunk [128 rows x BK], transposed, split hi/lo
        #pragma unroll
        for (int s = 0; s < 8; s++) {
            int idx = tid + s * 256;
            int kk = idx & 15;
            int r  = idx >> 4;
            int grow = row0 + r;
            float a = (grow < M) ? A[(size_t)grow * HH + k0 + kk] : 0.0f;
            u32 ahb = f2tf32(a);
            float ahf = __uint_as_float(ahb);
            u32 alb = f2tf32(a - ahf);
            sAh[kk * SWS + r] = ahf;
            sAl[kk * SWS + r] = __uint_as_float(alb);
        }
        __syncthreads();

        #pragma unroll
        for (int ks = 0; ks < 2; ks++) {
            int kb = ks * 8;
            // B fragments for 4 ntiles (hi & lo)
            u32 bh[4][2], bl[4][2];
            #pragma unroll
            for (int nt = 0; nt < 4; nt++) {
                int cc = wc * 32 + nt * 8 + g;
                bh[nt][0] = __float_as_uint(sWh[(kb + tig) * SWS + cc]);
                bh[nt][1] = __float_as_uint(sWh[(kb + tig + 4) * SWS + cc]);
                bl[nt][0] = __float_as_uint(sWl[(kb + tig) * SWS + cc]);
                bl[nt][1] = __float_as_uint(sWl[(kb + tig + 4) * SWS + cc]);
            }
            #pragma unroll
            for (int mt = 0; mt < 4; mt++) {
                int rr = wr * 64 + mt * 16 + g;
                u32 ah[4], al[4];
                ah[0] = __float_as_uint(sAh[(kb + tig) * SWS + rr]);
                ah[1] = __float_as_uint(sAh[(kb + tig) * SWS + rr + 8]);
                ah[2] = __float_as_uint(sAh[(kb + tig + 4) * SWS + rr]);
                ah[3] = __float_as_uint(sAh[(kb + tig + 4) * SWS + rr + 8]);
                al[0] = __float_as_uint(sAl[(kb + tig) * SWS + rr]);
                al[1] = __float_as_uint(sAl[(kb + tig) * SWS + rr + 8]);
                al[2] = __float_as_uint(sAl[(kb + tig + 4) * SWS + rr]);
                al[3] = __float_as_uint(sAl[(kb + tig + 4) * SWS + rr + 8]);
                #pragma unroll
                for (int nt = 0; nt < 4; nt++) {
                    mma_tf32(d[mt][nt], ah, bh[nt]);
                    mma_tf32(d[mt][nt], ah, bl[nt]);
                    mma_tf32(d[mt][nt], al, bh[nt]);
                }
            }
        }
    }

    // epilogue params per ntile (two adjacent cols per thread)
    float2 bb[4], ssv[4], ttv[4];
    #pragma unroll
    for (int nt = 0; nt < 4; nt++) {
        int c = wc * 32 + nt * 8 + 2 * tig;
        bb[nt] = *(const float2*)(bias + c);
        if (MODE == 1) {
            float2 bv = *(const float2*)(bn_v + c);
            float2 bg = *(const float2*)(bn_g + c);
            float2 bm = *(const float2*)(bn_m + c);
            float2 bbeta = *(const float2*)(bn_b + c);
            float i0 = rsqrtf(fabsf(bv.x) + 1e-5f);
            float i1 = rsqrtf(fabsf(bv.y) + 1e-5f);
            ssv[nt].x = bg.x * i0;
            ssv[nt].y = bg.y * i1;
            ttv[nt].x = bbeta.x - bm.x * ssv[nt].x;
            ttv[nt].y = bbeta.y - bm.y * ssv[nt].y;
        }
    }

    #pragma unroll
    for (int mt = 0; mt < 4; mt++) {
        int r0 = row0 + wr * 64 + mt * 16 + g;
        int r1 = r0 + 8;
        long long b0 = 0, b1 = 0;
        if (POOL) {
            if (g_idx64) {
                if (r0 < M) b0 = __ldg((const long long*)batch_raw + r0);
                if (r1 < M) b1 = __ldg((const long long*)batch_raw + r1);
            } else {
                if (r0 < M) b0 = __ldg((const int*)batch_raw + r0);
                if (r1 < M) b1 = __ldg((const int*)batch_raw + r1);
            }
        }
        #pragma unroll
        for (int nt = 0; nt < 4; nt++) {
            int c = wc * 32 + nt * 8 + 2 * tig;
            float z0 = d[mt][nt][0] + bb[nt].x;
            float z1 = d[mt][nt][1] + bb[nt].y;
            float z2 = d[mt][nt][2] + bb[nt].x;
            float z3 = d[mt][nt][3] + bb[nt].y;
            if (MODE == 1) {
                z0 = fmaf(z0, ssv[nt].x, ttv[nt].x);
                z1 = fmaf(z1, ssv[nt].y, ttv[nt].y);
                z2 = fmaf(z2, ssv[nt].x, ttv[nt].x);
                z3 = fmaf(z3, ssv[nt].y, ttv[nt].y);
            }
            z0 = fmaxf(z0, 0.0f); z1 = fmaxf(z1, 0.0f);
            z2 = fmaxf(z2, 0.0f); z3 = fmaxf(z3, 0.0f);
            if (POOL) {
                if (r0 < M && (unsigned long long)b0 < (unsigned long long)GG)
                    red_add_v2(g_pool + (size_t)b0 * HH + c, z0, z1);
                if (r1 < M && (unsigned long long)b1 < (unsigned long long)GG)
                    red_add_v2(g_pool + (size_t)b1 * HH + c, z2, z3);
            } else {
                if (r0 < M) {
                    float2* p = (float2*)(C + (size_t)r0 * HH + c);
                    *p = make_float2(z0, z1);
                }
                if (r1 < M) {
                    float2* p = (float2*)(C + (size_t)r1 * HH + c);
                    *p = make_float2(z2, z3);
                }
            }
        }
    }
}

// ---------------------------------------------------------------------------
__global__ void zero_pool_kernel() {
    int i = blockIdx.x * blockDim.x + threadIdx.x;
    if (i < GG * HH) g_pool[i] = 0.0f;
    if (i < GG) g_cnt[i] = 0.0f;
}

__global__ void cnt_kernel(const void* __restrict__ batch_raw, int n) {
    int i = blockIdx.x * blockDim.x + threadIdx.x;
    if (i >= n) return;
    long long b;
    if (g_idx64) b = __ldg((const long long*)batch_raw + i);
    else         b = __ldg((const int*)batch_raw + i);
    if ((unsigned long long)b < (unsigned long long)GG)
        atomicAdd(&g_cnt[b], 1.0f);
}

// ---------------------------------------------------------------------------
__global__ void classifier1_kernel(const float* __restrict__ cls_w1,
                                   const float* __restrict__ cls_b1) {
    __shared__ float sg[GG * HH];
    int tid = threadIdx.x;
    for (int i = tid; i < GG * HH; i += 256) {
        float cnt = g_cnt[i >> 7];
        sg[i] = g_pool[i] / fmaxf(cnt, 1.0f);
    }
    __syncthreads();
    for (int e = tid; e < GG * 64; e += 256) {
        int gi = e >> 6;
        int m  = e & 63;
        float s = cls_b1[m];
        #pragma unroll 8
        for (int k = 0; k < HH; k++)
            s = fmaf(sg[gi * HH + k], cls_w1[k * 64 + m], s);
        g_st[e] = fmaxf(s, 0.0f);
    }
}

__global__ void classifier2_kernel(const float* __restrict__ cls_w2,
                                   const float* __restrict__ cls_b2,
                                   float* __restrict__ out) {
    int g = threadIdx.x;
    if (g < GG) {
        float s = cls_b2[0];
        #pragma unroll 8
        for (int m = 0; m < 64; m++)
            s = fmaf(g_st[g * 64 + m], cls_w2[m], s);
        out[g] = 1.0f / (1.0f + expf(-s));
    }
}

// ---------------------------------------------------------------------------
extern "C" void kernel_launch(void* const* d_in, const int* in_sizes, int n_in,
                              void* d_out, int out_size) {
    const float *x, *edge_attr, *enc_w, *enc_b, *edge_w, *edge_b, *eps;
    const float *mlp_w1, *mlp_b1, *mlp_w2, *mlp_b2;
    const float *bn_gamma, *bn_beta, *bn_mean, *bn_var;
    const float *cls_w1, *cls_b1, *cls_w2, *cls_b2;
    const void *edge_index, *batch;
    int n, E;

    if (in_sizes[1] > 1000) {
        x          = (const float*)d_in[0];
        edge_index = d_in[1];
        edge_attr  = (const float*)d_in[2];
        batch      = d_in[3];
        enc_w      = (const float*)d_in[4];
        enc_b      = (const float*)d_in[5];
        edge_w     = (const float*)d_in[6];
        edge_b     = (const float*)d_in[7];
        eps        = (const float*)d_in[8];
        mlp_w1     = (const float*)d_in[9];
        mlp_b1     = (const float*)d_in[10];
        mlp_w2     = (const float*)d_in[11];
        mlp_b2     = (const float*)d_in[12];
        bn_gamma   = (const float*)d_in[13];
        bn_beta    = (const float*)d_in[14];
        bn_mean    = (const float*)d_in[15];
        bn_var     = (const float*)d_in[16];
        cls_w1     = (const float*)d_in[17];
        cls_b1     = (const float*)d_in[18];
        cls_w2     = (const float*)d_in[19];
        cls_b2     = (const float*)d_in[20];
        n = in_sizes[0];
        E = in_sizes[2];
    } else {
        batch      = d_in[0];
        bn_beta    = (const float*)d_in[1];
        bn_gamma   = (const float*)d_in[2];
        bn_mean    = (const float*)d_in[3];
        bn_var     = (const float*)d_in[4];
        cls_b1     = (const float*)d_in[5];
        cls_b2     = (const float*)d_in[6];
        cls_w1     = (const float*)d_in[7];
        cls_w2     = (const float*)d_in[8];
        edge_attr  = (const float*)d_in[9];
        edge_b     = (const float*)d_in[10];
        edge_index = d_in[11];
        edge_w     = (const float*)d_in[12];
        enc_b      = (const float*)d_in[13];
        enc_w      = (const float*)d_in[14];
        eps        = (const float*)d_in[15];
        mlp_b1     = (const float*)d_in[16];
        mlp_b2     = (const float*)d_in[17];
        mlp_w1     = (const float*)d_in[18];
        mlp_w2     = (const float*)d_in[19];
        x          = (const float*)d_in[20];
        n = in_sizes[20];
        E = in_sizes[9];
    }
    float* out = (float*)d_out;
    if (E > EE_MAX) E = EE_MAX;

    // 0) dtype detect + pool zero + per-graph counts
    detect_kernel<<<1, 32>>>(edge_index, n);
    zero_pool_kernel<<<(GG * HH + 255) / 256, 256>>>();
    cnt_kernel<<<(n + 255) / 256, 256>>>(batch, n);

    // 1) CSR build
    int nblk = (n + 255) / 256;
    zero_deg_kernel<<<nblk, 256>>>(n);
    csr_count_kernel<<<(E + 255) / 256, 256>>>(edge_index, E, n);
    blocksum_kernel<<<nblk, 256>>>(n);
    scan_bsum_kernel<<<1, 512>>>(nblk);
    rowptr_kernel<<<nblk, 256>>>(n, E);
    csr_fill_kernel<<<(E + 255) / 256, 256>>>(edge_index, edge_attr, E, n);

    // 2) layers
    int gemm_blocks = (n + 127) / 128;
    int agg_blocks = (n * 32 + 255) / 256;

    // layer 0: rank-1 aggregate
    aggregate_l0_kernel<<<agg_blocks, 256>>>(x, enc_w, enc_b, edge_w, edge_b,
                                             eps, n);
    gemm128_kernel<0, BUF_AGGR, BUF_TMP, 0><<<gemm_blocks, 256>>>(
        mlp_w1, mlp_b1, nullptr, nullptr, nullptr, nullptr, nullptr, n);
    gemm128_kernel<1, BUF_TMP, BUF_H, 0><<<gemm_blocks, 256>>>(
        mlp_w2, mlp_b2, bn_gamma, bn_beta, bn_mean, bn_var, nullptr, n);

    // layer 1: dense aggregate + MLP; last GEMM pools directly
    aggregate_kernel<<<agg_blocks, 256>>>(edge_w, edge_b, eps + 1, n);
    gemm128_kernel<0, BUF_AGGR, BUF_TMP, 0><<<gemm_blocks, 256>>>(
        mlp_w1 + (size_t)HH * HH, mlp_b1 + HH,
        nullptr, nullptr, nullptr, nullptr, nullptr, n);
    gemm128_kernel<1, BUF_TMP, BUF_H, 1><<<gemm_blocks, 256>>>(
        mlp_w2 + (size_t)HH * HH, mlp_b2 + HH,
        bn_gamma + HH, bn_beta + HH, bn_mean + HH, bn_var + HH, batch, n);

    // 3) classifier
    classifier1_kernel<<<1, 256>>>(cls_w1, cls_b1);
    classifier2_kernel<<<1, 64>>>(cls_w2, cls_b2, out);
}